// round 3
// baseline (speedup 1.0000x reference)
#include <cuda_runtime.h>

#define B_ 4096
#define T_ 24
#define I_ 128
#define H_ 512
#define WD_ 32
#define M_ (B_*T_)   // 98304

typedef unsigned long long ull;

// ---------------- scratch (device globals; no allocation) ----------------
__device__ float g_e    [M_*H_];   // e = sigmoid(xw @ w_e^T + b_e), [B*T, H]
__device__ float g_pre_o[M_*H_];   // [T, B, H]
__device__ float g_pre_r[M_*H_];
__device__ float g_pre_z[M_*H_];
__device__ float g_pre_h[M_*H_];
__device__ float g_h [B_*H_];
__device__ float g_ho[B_*H_];
__device__ float g_a [B_*H_];      // r * h_o
__device__ float g_z [B_*H_];
__device__ float g_Wrz [1024*640]; // [[w_rx|w_re];[w_zx|w_ze]]
__device__ float g_Wo  [512*384];  // [w_d|w_w|w_m]
__device__ float g_Wrzh[1024*512]; // [w_rh; w_zh]

__device__ __forceinline__ float sigf(float x){ return 1.f/(1.f + __expf(-x)); }

__device__ __forceinline__ void fma2(ull& d, ull a, ull b){
    asm("fma.rn.f32x2 %0, %1, %2, %0;" : "+l"(d) : "l"(a), "l"(b));
}
__device__ __forceinline__ ull pack2(float x){
    ull r; asm("mov.b64 %0, {%1, %1};" : "=l"(r) : "f"(x)); return r;
}

// ---------------- weight-concat + h0 init ----------------
__global__ void prep_k(const float* __restrict__ w_rx, const float* __restrict__ w_re,
                       const float* __restrict__ w_zx, const float* __restrict__ w_ze,
                       const float* __restrict__ w_d,  const float* __restrict__ w_w,
                       const float* __restrict__ w_m,
                       const float* __restrict__ w_rh, const float* __restrict__ w_zh)
{
    int i = blockIdx.x*blockDim.x + threadIdx.x;
    if (i < 1024*640){
        int r = i/640, c = i - r*640;
        float v;
        if (r < 512) v = (c < 128) ? w_rx[r*128+c] : w_re[r*512 + (c-128)];
        else { int rr = r-512; v = (c < 128) ? w_zx[rr*128+c] : w_ze[rr*512 + (c-128)]; }
        g_Wrz[i] = v;
    }
    if (i < 512*384){
        int r = i/384, c = i - r*384;
        int s = c >> 7, cc = c & 127;
        const float* p = (s==0) ? w_d : (s==1) ? w_w : w_m;
        g_Wo[i] = p[r*128+cc];
    }
    if (i < 1024*512){
        int r = i >> 9, c = i & 511;
        g_Wrzh[i] = (r < 512) ? w_rh[r*512+c] : w_zh[(r-512)*512+c];
    }
    if (i < B_*H_) g_h[i] = 0.f;
}

// ---------------- generic tiled GEMM: C = epilogue(A @ W^T) ----------------
// MODE 0: e      A=xw [M,32]      W=w_e                 -> g_e = sig(c + b_e)
// MODE 1: pre_rz A=[x|e] K=640    W=g_Wrz, N=1024       -> g_pre_r/g_pre_z (+bias), [T,B,H]
// MODE 2: pre_o  A=shifted x K=384 W=g_Wo               -> g_pre_o, [T,B,H]
// MODE 3: pre_h  A=x K=128        W=w_hx                -> g_pre_h (+b_h), [T,B,H]
// MODE 4: R1     A=g_h K=512      W=w_t                 -> g_ho = sig(pre_o_t + c)
// MODE 5: R2     A=g_ho K=512     W=g_Wrzh, N=1024      -> g_a = sig(pre_r_t+c)*g_ho ; g_z = sig(pre_z_t+c)
// MODE 6: R3     A=g_a K=512      W=w_hh                -> h = (1-z)*ho + z*tanh(pre_h_t+c); write h, out
template<int MODE>
__global__ void __launch_bounds__(256, 2)
gemm_k(const float* __restrict__ A, const float* __restrict__ W,
       const float* __restrict__ bias, const float* __restrict__ bias2,
       float* __restrict__ out, int K, int t)
{
    __shared__ float As[16][128];
    __shared__ float Bs[16][128];
    const int tid = threadIdx.x;
    const int tr = tid >> 4, tc = tid & 15;
    const int m0 = tr * 8, n0 = tc * 8;
    const int bm = blockIdx.y * 128, bn = blockIdx.x * 128;

    const float* Wp = (MODE==1) ? g_Wrz : (MODE==2) ? g_Wo : (MODE==5) ? g_Wrzh : W;

    ull acc[8][4];
#pragma unroll
    for (int i=0;i<8;i++)
#pragma unroll
        for (int j=0;j<4;j++) acc[i][j] = 0ull;

    for (int k0 = 0; k0 < K; k0 += 16){
#pragma unroll
        for (int it = 0; it < 2; it++){
            int id = tid + it*256;
            int r  = id >> 2, c4 = id & 3;
            int kk = k0 + c4*4;
            int gm = bm + r;
            float4 v;
            if (MODE==0)      v = *(const float4*)(A + gm*WD_ + kk);
            else if (MODE==1) v = (kk < I_) ? *(const float4*)(A + gm*I_ + kk)
                                            : *(const float4*)(g_e + gm*H_ + (kk - I_));
            else if (MODE==2){
                int s = kk >> 7;
                int shift = (s==0) ? 1 : (s==1) ? 7 : 30;
                int b = gm / T_;
                if (b < shift) v = make_float4(0.f,0.f,0.f,0.f);
                else           v = *(const float4*)(A + (gm - shift*T_)*I_ + (kk & 127));
            }
            else if (MODE==3) v = *(const float4*)(A + gm*I_ + kk);
            else if (MODE==4) v = *(const float4*)(g_h  + gm*H_ + kk);
            else if (MODE==5) v = *(const float4*)(g_ho + gm*H_ + kk);
            else              v = *(const float4*)(g_a  + gm*H_ + kk);
            As[c4*4+0][r]=v.x; As[c4*4+1][r]=v.y; As[c4*4+2][r]=v.z; As[c4*4+3][r]=v.w;

            int gn = bn + r;
            float4 w = *(const float4*)(Wp + gn*K + kk);
            Bs[c4*4+0][r]=w.x; Bs[c4*4+1][r]=w.y; Bs[c4*4+2][r]=w.z; Bs[c4*4+3][r]=w.w;
        }
        __syncthreads();
#pragma unroll
        for (int k = 0; k < 16; k++){
            float4 a0 = *(const float4*)&As[k][m0];
            float4 a1 = *(const float4*)&As[k][m0+4];
            float4 b0 = *(const float4*)&Bs[k][n0];
            float4 b1 = *(const float4*)&Bs[k][n0+4];
            ull bp[4];
            bp[0]=((ull*)&b0)[0]; bp[1]=((ull*)&b0)[1];
            bp[2]=((ull*)&b1)[0]; bp[3]=((ull*)&b1)[1];
            float av[8] = {a0.x,a0.y,a0.z,a0.w,a1.x,a1.y,a1.z,a1.w};
#pragma unroll
            for (int i=0;i<8;i++){
                ull ap = pack2(av[i]);
                fma2(acc[i][0], ap, bp[0]);
                fma2(acc[i][1], ap, bp[1]);
                fma2(acc[i][2], ap, bp[2]);
                fma2(acc[i][3], ap, bp[3]);
            }
        }
        __syncthreads();
    }

    // -------- epilogue --------
#pragma unroll
    for (int i=0;i<8;i++){
        int gm = bm + m0 + i;
        float cf[8];
#pragma unroll
        for (int j=0;j<4;j++){
            cf[2*j]   = __uint_as_float((unsigned)(acc[i][j] & 0xffffffffull));
            cf[2*j+1] = __uint_as_float((unsigned)(acc[i][j] >> 32));
        }
#pragma unroll
        for (int j=0;j<8;j++){
            int gn = bn + n0 + j;
            float c = cf[j];
            if (MODE==0){
                g_e[gm*H_+gn] = sigf(c + bias[gn]);
            } else if (MODE==1){
                int b = gm / T_, tt = gm - b*T_;
                int base = (tt*B_ + b)*H_;
                if (gn < H_) g_pre_r[base + gn]      = c + bias [gn];
                else         g_pre_z[base + gn - H_] = c + bias2[gn - H_];
            } else if (MODE==2){
                int b = gm / T_, tt = gm - b*T_;
                g_pre_o[(tt*B_+b)*H_ + gn] = c;
            } else if (MODE==3){
                int b = gm / T_, tt = gm - b*T_;
                g_pre_h[(tt*B_+b)*H_ + gn] = c + bias[gn];
            } else if (MODE==4){
                g_ho[gm*H_+gn] = sigf(g_pre_o[(t*B_+gm)*H_+gn] + c);
            } else if (MODE==5){
                if (gn < H_){
                    float r = sigf(g_pre_r[(t*B_+gm)*H_+gn] + c);
                    g_a[gm*H_+gn] = r * g_ho[gm*H_+gn];
                } else {
                    int n2 = gn - H_;
                    g_z[gm*H_+n2] = sigf(g_pre_z[(t*B_+gm)*H_+n2] + c);
                }
            } else { // MODE 6
                int idx = gm*H_+gn;
                float ht = tanhf(g_pre_h[(t*B_+gm)*H_+gn] + c);
                float z  = g_z[idx], ho = g_ho[idx];
                float hn = (1.f - z)*ho + z*ht;
                g_h[idx] = hn;
                out[(gm*T_ + t)*H_ + gn] = hn;
            }
        }
    }
}

// ---------------- launcher ----------------
extern "C" void kernel_launch(void* const* d_in, const int* in_sizes, int n_in,
                              void* d_out, int out_size)
{
    const float* x    = (const float*)d_in[0];
    const float* xw   = (const float*)d_in[1];
    const float* w_rx = (const float*)d_in[2];
    const float* w_rh = (const float*)d_in[3];
    const float* w_re = (const float*)d_in[4];
    const float* b_r  = (const float*)d_in[5];
    const float* w_zx = (const float*)d_in[6];
    const float* w_zh = (const float*)d_in[7];
    const float* w_ze = (const float*)d_in[8];
    const float* b_z  = (const float*)d_in[9];
    const float* w_hx = (const float*)d_in[10];
    const float* w_hh = (const float*)d_in[11];
    const float* b_h  = (const float*)d_in[12];
    const float* w_d  = (const float*)d_in[13];
    const float* w_w  = (const float*)d_in[14];
    const float* w_m  = (const float*)d_in[15];
    const float* w_t  = (const float*)d_in[16];
    const float* w_e  = (const float*)d_in[17];
    const float* b_e  = (const float*)d_in[18];
    float* out = (float*)d_out;

    prep_k<<<(B_*H_+255)/256, 256>>>(w_rx,w_re,w_zx,w_ze,w_d,w_w,w_m,w_rh,w_zh);

    // precompute (M = 98304 rows)
    gemm_k<0><<<dim3(4,768), 256>>>(xw, w_e, b_e, nullptr, nullptr,  32, 0);
    gemm_k<1><<<dim3(8,768), 256>>>(x, nullptr, b_r, b_z, nullptr, 640, 0);
    gemm_k<2><<<dim3(4,768), 256>>>(x, nullptr, nullptr, nullptr, nullptr, 384, 0);
    gemm_k<3><<<dim3(4,768), 256>>>(x, w_hx, b_h, nullptr, nullptr, 128, 0);

    // recurrence (M = 4096 rows per step)
    for (int t = 0; t < T_; t++){
        gemm_k<4><<<dim3(4,32), 256>>>(nullptr, w_t,  nullptr, nullptr, nullptr, 512, t);
        gemm_k<5><<<dim3(8,32), 256>>>(nullptr, nullptr, nullptr, nullptr, nullptr, 512, t);
        gemm_k<6><<<dim3(4,32), 256>>>(nullptr, w_hh, nullptr, nullptr, out, 512, t);
    }
}

// round 5
// speedup vs baseline: 1.3411x; 1.3411x over previous
#include <cuda_runtime.h>
#include <cuda_bf16.h>
#include <cstdint>

#define B_ 4096
#define T_ 24
#define I_ 128
#define H_ 512
#define WD_ 32
#define M_ (B_*T_)

typedef unsigned int u32; typedef unsigned long long u64; typedef __nv_bfloat16 bf16;

// ---------- scratch (device globals; [0]=hi, [1]=lo) ----------
__device__ __align__(16) bf16 g_x[2][M_*I_], g_xw[2][M_*WD_], g_e[2][M_*H_];
__device__ __align__(16) float g_pre_o[M_*H_], g_pre_r[M_*H_], g_pre_z[M_*H_], g_pre_h[M_*H_];
__device__ __align__(16) bf16 g_h[2][B_*H_], g_hob[2][B_*H_], g_ab[2][B_*H_];
__device__ __align__(16) float g_ho[B_*H_], g_z[B_*H_];
__device__ __align__(16) bf16 g_Wrz[2][1024*640], g_Wo[2][512*384], g_Whx[2][512*128];
__device__ __align__(16) bf16 g_Wt[2][512*512], g_Wrzh[2][1024*512], g_Whh[2][512*512], g_We[2][512*WD_];

__device__ __forceinline__ float sigf(float x){ return 1.f/(1.f + __expf(-x)); }
__device__ __forceinline__ void spst(bf16* hi, bf16* lo, int idx, float v){
    bf16 h = __float2bfloat16(v);
    hi[idx] = h; lo[idx] = __float2bfloat16(v - __bfloat162float(h));
}
__device__ __forceinline__ u32 s2u(const void* p){
    u32 a; asm("{ .reg .u64 t; cvta.to.shared.u64 t, %1; cvt.u32.u64 %0, t; }" : "=r"(a) : "l"(p)); return a;
}
__device__ __forceinline__ void ldsm4(u32* r, u32 addr){
    asm volatile("ldmatrix.sync.aligned.m8n8.x4.shared.b16 {%0,%1,%2,%3}, [%4];"
        : "=r"(r[0]), "=r"(r[1]), "=r"(r[2]), "=r"(r[3]) : "r"(addr));
}
__device__ __forceinline__ void mmab(float* c, const u32* a, const u32* b){
    asm volatile("mma.sync.aligned.m16n8k16.row.col.f32.bf16.bf16.f32 "
        "{%0,%1,%2,%3}, {%4,%5,%6,%7}, {%8,%9}, {%0,%1,%2,%3};"
        : "+f"(c[0]), "+f"(c[1]), "+f"(c[2]), "+f"(c[3])
        : "r"(a[0]), "r"(a[1]), "r"(a[2]), "r"(a[3]), "r"(b[0]), "r"(b[1]));
}

// ---------- prep: fp32 -> bf16 hi/lo + weight concat ----------
__global__ void prep_k(const float* __restrict__ x, const float* __restrict__ xw,
    const float* __restrict__ w_rx, const float* __restrict__ w_rh, const float* __restrict__ w_re,
    const float* __restrict__ w_zx, const float* __restrict__ w_zh, const float* __restrict__ w_ze,
    const float* __restrict__ w_hx, const float* __restrict__ w_hh,
    const float* __restrict__ w_d,  const float* __restrict__ w_w,  const float* __restrict__ w_m,
    const float* __restrict__ w_t,  const float* __restrict__ w_e)
{
    int i = blockIdx.x*256 + threadIdx.x;
    if (i < M_*I_)  spst(g_x[0],  g_x[1],  i, x[i]);
    if (i < M_*WD_) spst(g_xw[0], g_xw[1], i, xw[i]);
    if (i < B_*H_){ g_h[0][i] = __float2bfloat16(0.f); g_h[1][i] = __float2bfloat16(0.f); }
    if (i < 1024*640){
        int r = i/640, c = i - r*640; float v;
        if (r < 512) v = (c < 128) ? w_rx[r*128+c] : w_re[r*512 + c - 128];
        else { int rr = r-512; v = (c < 128) ? w_zx[rr*128+c] : w_ze[rr*512 + c - 128]; }
        spst(g_Wrz[0], g_Wrz[1], i, v);
    }
    if (i < 512*384){
        int r = i/384, c = i - r*384; int s = c >> 7;
        const float* p = (s==0) ? w_d : (s==1) ? w_w : w_m;
        spst(g_Wo[0], g_Wo[1], i, p[r*128 + (c & 127)]);
    }
    if (i < 512*128) spst(g_Whx[0], g_Whx[1], i, w_hx[i]);
    if (i < 512*512){ spst(g_Wt[0], g_Wt[1], i, w_t[i]); spst(g_Whh[0], g_Whh[1], i, w_hh[i]); }
    if (i < 1024*512){
        int r = i >> 9, c = i & 511;
        spst(g_Wrzh[0], g_Wrzh[1], i, (r < 512) ? w_rh[r*512+c] : w_zh[(r-512)*512+c]);
    }
    if (i < 512*WD_) spst(g_We[0], g_We[1], i, w_e[i]);
}

// ---------- HMMA GEMM: 128x128 tile, K chunks of 64, bf16x3 split ----------
// smem layout: Ah[128][72] | Al | Bh[128][72] | Bl   (rows padded to 144B)
#define RSTB 144
#define REG_ 18432   // 128*144
template<int MODE, int K, int CH>
__global__ void __launch_bounds__(256)
mm_k(const float* __restrict__ bias, const float* __restrict__ bias2,
     float* __restrict__ out, int t)
{
    extern __shared__ __align__(128) char sm_[];
    const int tid = threadIdx.x, lane = tid & 31, wid = tid >> 5;
    const int bm = blockIdx.y*128, bn = blockIdx.x*128;
    const int m0 = (wid >> 1)*32, n0 = (wid & 1)*64;
    char* sA = sm_;
    char* sB = sm_ + 2*REG_;
    const u32 sAu = s2u(sA), sBu = s2u(sB);

    const bf16 *BH, *BL;
    if      (MODE==0){ BH=g_We[0];   BL=g_We[1];   }
    else if (MODE==1){ BH=g_Wrz[0];  BL=g_Wrz[1];  }
    else if (MODE==2){ BH=g_Wo[0];   BL=g_Wo[1];   }
    else if (MODE==3){ BH=g_Whx[0];  BL=g_Whx[1];  }
    else if (MODE==4){ BH=g_Wt[0];   BL=g_Wt[1];   }
    else if (MODE==5){ BH=g_Wrzh[0]; BL=g_Wrzh[1]; }
    else             { BH=g_Whh[0];  BL=g_Whh[1];  }

    float acc[2][8][4];
#pragma unroll
    for (int a=0;a<2;a++)
#pragma unroll
        for (int b=0;b<8;b++)
#pragma unroll
            for (int c=0;c<4;c++) acc[a][b][c] = 0.f;

    // per-lane ldmatrix base addresses
    const u32 aB = sAu + (u32)((m0 + (lane&7) + ((lane>>3)&1)*8)*RSTB + ((lane>>4)&1)*16);
    const u32 bBa = sBu + (u32)((n0 + (lane&7) + ((lane>>4)&1)*8)*RSTB + ((lane>>3)&1)*16);

#pragma unroll 1
    for (int ch = 0; ch < CH; ch++){
        const int k0 = ch*64;
        // ---- A tile: 128 rows x 64 cols (hi+lo) ----
#pragma unroll 1
        for (int g = tid; g < 1024; g += 256){
            int r = g >> 3, kk = k0 + (g & 7)*8, gm = bm + r;
            uint4 vh = make_uint4(0,0,0,0), vl = vh;
            if (MODE == 0){
                if (kk < WD_){ int s0 = gm*WD_ + kk; vh = *(const uint4*)(g_xw[0]+s0); vl = *(const uint4*)(g_xw[1]+s0); }
            } else if (MODE == 1){
                if (kk < I_){ int s0 = gm*I_ + kk; vh = *(const uint4*)(g_x[0]+s0); vl = *(const uint4*)(g_x[1]+s0); }
                else { int s0 = gm*H_ + kk - I_; vh = *(const uint4*)(g_e[0]+s0); vl = *(const uint4*)(g_e[1]+s0); }
            } else if (MODE == 2){
                int seg = kk >> 7, sh = (seg==0) ? 1 : (seg==1) ? 7 : 30;
                int b = gm / T_;
                if (b >= sh){ int s0 = (gm - sh*T_)*I_ + (kk & 127); vh = *(const uint4*)(g_x[0]+s0); vl = *(const uint4*)(g_x[1]+s0); }
            } else if (MODE == 3){
                int s0 = gm*I_ + kk; vh = *(const uint4*)(g_x[0]+s0); vl = *(const uint4*)(g_x[1]+s0);
            } else if (MODE == 4){
                int s0 = gm*H_ + kk; vh = *(const uint4*)(g_h[0]+s0); vl = *(const uint4*)(g_h[1]+s0);
            } else if (MODE == 5){
                int s0 = gm*H_ + kk; vh = *(const uint4*)(g_hob[0]+s0); vl = *(const uint4*)(g_hob[1]+s0);
            } else {
                int s0 = gm*H_ + kk; vh = *(const uint4*)(g_ab[0]+s0); vl = *(const uint4*)(g_ab[1]+s0);
            }
            int off = r*RSTB + (g & 7)*16;
            *(uint4*)(sA + off) = vh; *(uint4*)(sA + REG_ + off) = vl;
        }
        // ---- B tile: 128 rows x 64 cols (hi+lo) ----
#pragma unroll 1
        for (int g = tid; g < 1024; g += 256){
            int r = g >> 3, kk = k0 + (g & 7)*8, gn = bn + r;
            uint4 vh = make_uint4(0,0,0,0), vl = vh;
            if (MODE != 0 || kk < WD_){
                int s0 = gn*K + kk; vh = *(const uint4*)(BH + s0); vl = *(const uint4*)(BL + s0);
            }
            int off = r*RSTB + (g & 7)*16;
            *(uint4*)(sB + off) = vh; *(uint4*)(sB + REG_ + off) = vl;
        }
        __syncthreads();

        // ---- 3 split-products ----
#pragma unroll
        for (int p = 0; p < 3; p++){
            const u32 ab = aB + ((p == 2) ? (u32)REG_ : 0u);
            const u32 bb = bBa + ((p == 1) ? (u32)REG_ : 0u);
#pragma unroll
            for (int ks = 0; ks < 4; ks++){
                u32 a0[4], a1[4], bq[4][4];
                ldsm4(a0, ab + ks*32);
                ldsm4(a1, ab + 16*RSTB + ks*32);
#pragma unroll
                for (int nq = 0; nq < 4; nq++) ldsm4(bq[nq], bb + nq*16*RSTB + ks*32);
#pragma unroll
                for (int ni = 0; ni < 8; ni++){
                    const u32* bp = &bq[ni>>1][(ni&1)*2];
                    mmab(acc[0][ni], a0, bp);
                    mmab(acc[1][ni], a1, bp);
                }
            }
        }
        __syncthreads();
    }

    // ---------- epilogue ----------
#pragma unroll
    for (int mi = 0; mi < 2; mi++){
#pragma unroll
        for (int half = 0; half < 2; half++){
            const int gm = bm + m0 + mi*16 + (lane>>2) + half*8;
#pragma unroll
            for (int ni = 0; ni < 8; ni++){
                const int gn = bn + n0 + ni*8 + (lane&3)*2;
                float v0 = acc[mi][ni][half*2+0];
                float v1 = acc[mi][ni][half*2+1];
                if (MODE == 0){
                    spst(g_e[0], g_e[1], gm*H_+gn,   sigf(v0 + bias[gn]));
                    spst(g_e[0], g_e[1], gm*H_+gn+1, sigf(v1 + bias[gn+1]));
                } else if (MODE == 1){
                    int b = gm/T_, tt = gm - b*T_; int base = (tt*B_ + b)*H_;
                    if (gn < H_){
                        g_pre_r[base+gn]   = v0 + bias[gn];
                        g_pre_r[base+gn+1] = v1 + bias[gn+1];
                    } else {
                        g_pre_z[base+gn-H_]   = v0 + bias2[gn-H_];
                        g_pre_z[base+gn-H_+1] = v1 + bias2[gn-H_+1];
                    }
                } else if (MODE == 2){
                    int b = gm/T_, tt = gm - b*T_; int base = (tt*B_ + b)*H_;
                    g_pre_o[base+gn] = v0; g_pre_o[base+gn+1] = v1;
                } else if (MODE == 3){
                    int b = gm/T_, tt = gm - b*T_; int base = (tt*B_ + b)*H_;
                    g_pre_h[base+gn] = v0 + bias[gn];
                    g_pre_h[base+gn+1] = v1 + bias[gn+1];
                } else if (MODE == 4){
                    int pb = (t*B_ + gm)*H_ + gn, hb = gm*H_ + gn;
                    float h0 = sigf(g_pre_o[pb]   + v0);
                    float h1 = sigf(g_pre_o[pb+1] + v1);
                    g_ho[hb] = h0; g_ho[hb+1] = h1;
                    spst(g_hob[0], g_hob[1], hb,   h0);
                    spst(g_hob[0], g_hob[1], hb+1, h1);
                } else if (MODE == 5){
                    if (gn < H_){
                        int pb = (t*B_ + gm)*H_ + gn, hb = gm*H_ + gn;
                        float r0 = sigf(g_pre_r[pb]   + v0);
                        float r1 = sigf(g_pre_r[pb+1] + v1);
                        spst(g_ab[0], g_ab[1], hb,   r0 * g_ho[hb]);
                        spst(g_ab[0], g_ab[1], hb+1, r1 * g_ho[hb+1]);
                    } else {
                        int n2 = gn - H_;
                        int pb = (t*B_ + gm)*H_ + n2, hb = gm*H_ + n2;
                        g_z[hb]   = sigf(g_pre_z[pb]   + v0);
                        g_z[hb+1] = sigf(g_pre_z[pb+1] + v1);
                    }
                } else {
                    int pb = (t*B_ + gm)*H_ + gn, hb = gm*H_ + gn;
                    float h0, h1;
                    {
                        float ht = tanhf(g_pre_h[pb] + v0);
                        float z = g_z[hb];
                        h0 = (1.f - z)*g_ho[hb] + z*ht;
                    }
                    {
                        float ht = tanhf(g_pre_h[pb+1] + v1);
                        float z = g_z[hb+1];
                        h1 = (1.f - z)*g_ho[hb+1] + z*ht;
                    }
                    spst(g_h[0], g_h[1], hb,   h0);
                    spst(g_h[0], g_h[1], hb+1, h1);
                    out[(gm*T_ + t)*H_ + gn]   = h0;
                    out[(gm*T_ + t)*H_ + gn+1] = h1;
                }
            }
        }
    }
}

// ---------- launcher ----------
#define SMB (4*REG_)   // 73728
extern "C" void kernel_launch(void* const* d_in, const int* in_sizes, int n_in,
                              void* d_out, int out_size)
{
    const float* x    = (const float*)d_in[0];
    const float* xw   = (const float*)d_in[1];
    const float* w_rx = (const float*)d_in[2];
    const float* w_rh = (const float*)d_in[3];
    const float* w_re = (const float*)d_in[4];
    const float* b_r  = (const float*)d_in[5];
    const float* w_zx = (const float*)d_in[6];
    const float* w_zh = (const float*)d_in[7];
    const float* w_ze = (const float*)d_in[8];
    const float* b_z  = (const float*)d_in[9];
    const float* w_hx = (const float*)d_in[10];
    const float* w_hh = (const float*)d_in[11];
    const float* b_h  = (const float*)d_in[12];
    const float* w_d  = (const float*)d_in[13];
    const float* w_w  = (const float*)d_in[14];
    const float* w_m  = (const float*)d_in[15];
    const float* w_t  = (const float*)d_in[16];
    const float* w_e  = (const float*)d_in[17];
    const float* b_e  = (const float*)d_in[18];
    float* out = (float*)d_out;

    static int init = 0;
    if (!init){
        cudaFuncSetAttribute(mm_k<0, 32, 1>, cudaFuncAttributeMaxDynamicSharedMemorySize, SMB);
        cudaFuncSetAttribute(mm_k<1,640,10>, cudaFuncAttributeMaxDynamicSharedMemorySize, SMB);
        cudaFuncSetAttribute(mm_k<2,384, 6>, cudaFuncAttributeMaxDynamicSharedMemorySize, SMB);
        cudaFuncSetAttribute(mm_k<3,128, 2>, cudaFuncAttributeMaxDynamicSharedMemorySize, SMB);
        cudaFuncSetAttribute(mm_k<4,512, 8>, cudaFuncAttributeMaxDynamicSharedMemorySize, SMB);
        cudaFuncSetAttribute(mm_k<5,512, 8>, cudaFuncAttributeMaxDynamicSharedMemorySize, SMB);
        cudaFuncSetAttribute(mm_k<6,512, 8>, cudaFuncAttributeMaxDynamicSharedMemorySize, SMB);
        init = 1;
    }

    prep_k<<<(M_*I_ + 255)/256, 256>>>(x, xw, w_rx, w_rh, w_re, w_zx, w_zh, w_ze,
                                       w_hx, w_hh, w_d, w_w, w_m, w_t, w_e);

    mm_k<0, 32, 1><<<dim3(4,768), 256, SMB>>>(b_e, nullptr, nullptr, 0);
    mm_k<1,640,10><<<dim3(8,768), 256, SMB>>>(b_r, b_z,    nullptr, 0);
    mm_k<2,384, 6><<<dim3(4,768), 256, SMB>>>(nullptr, nullptr, nullptr, 0);
    mm_k<3,128, 2><<<dim3(4,768), 256, SMB>>>(b_h, nullptr, nullptr, 0);

    for (int t = 0; t < T_; t++){
        mm_k<4,512,8><<<dim3(4,32), 256, SMB>>>(nullptr, nullptr, nullptr, t);
        mm_k<5,512,8><<<dim3(8,32), 256, SMB>>>(nullptr, nullptr, nullptr, t);
        mm_k<6,512,8><<<dim3(4,32), 256, SMB>>>(nullptr, nullptr, out,     t);
    }
}

// round 6
// speedup vs baseline: 1.9550x; 1.4577x over previous
#include <cuda_runtime.h>
#include <cuda_bf16.h>
#include <cstdint>

#define B_ 4096
#define T_ 24
#define I_ 128
#define H_ 512
#define WD_ 32
#define M_ (B_*T_)

typedef unsigned int u32; typedef unsigned long long u64; typedef __nv_bfloat16 bf16;

// ---------- scratch (device globals; [0]=hi, [1]=lo) ----------
__device__ __align__(16) bf16 g_x[2][M_*I_], g_xw[2][M_*WD_], g_e[2][M_*H_];
__device__ __align__(16) float g_pre_o[M_*H_], g_pre_r[M_*H_], g_pre_z[M_*H_], g_pre_h[M_*H_];
__device__ __align__(16) bf16 g_h[2][B_*H_], g_hob[2][B_*H_], g_ab[2][B_*H_];
__device__ __align__(16) float g_ho[B_*H_], g_z[B_*H_];
__device__ __align__(16) bf16 g_Wrz[2][1024*640], g_Wo[2][512*384], g_Whx[2][512*128];
__device__ __align__(16) bf16 g_Wt[2][512*512], g_Wrzh[2][1024*512], g_Whh[2][512*512], g_We[2][512*WD_];

__device__ unsigned g_bcnt;
__device__ volatile unsigned g_bgen;

__device__ __forceinline__ float sigf(float x){ return 1.f/(1.f + __expf(-x)); }
__device__ __forceinline__ void spst(bf16* hi, bf16* lo, int idx, float v){
    bf16 h = __float2bfloat16(v);
    hi[idx] = h; lo[idx] = __float2bfloat16(v - __bfloat162float(h));
}
__device__ __forceinline__ u32 s2u(const void* p){
    u32 a; asm("{ .reg .u64 t; cvta.to.shared.u64 t, %1; cvt.u32.u64 %0, t; }" : "=r"(a) : "l"(p)); return a;
}
__device__ __forceinline__ void ldsm4(u32* r, u32 addr){
    asm volatile("ldmatrix.sync.aligned.m8n8.x4.shared.b16 {%0,%1,%2,%3}, [%4];"
        : "=r"(r[0]), "=r"(r[1]), "=r"(r[2]), "=r"(r[3]) : "r"(addr));
}
__device__ __forceinline__ void mmab(float* c, const u32* a, const u32* b){
    asm volatile("mma.sync.aligned.m16n8k16.row.col.f32.bf16.bf16.f32 "
        "{%0,%1,%2,%3}, {%4,%5,%6,%7}, {%8,%9}, {%0,%1,%2,%3};"
        : "+f"(c[0]), "+f"(c[1]), "+f"(c[2]), "+f"(c[3])
        : "r"(a[0]), "r"(a[1]), "r"(a[2]), "r"(a[3]), "r"(b[0]), "r"(b[1]));
}
__device__ __forceinline__ void cpa(u32 s, const void* g, int sz){
    asm volatile("cp.async.cg.shared.global [%0], [%1], 16, %2;" :: "r"(s), "l"(g), "r"(sz) : "memory");
}
__device__ __forceinline__ void cpcommit(){ asm volatile("cp.async.commit_group;" ::: "memory"); }
template<int N> __device__ __forceinline__ void cpwait(){ asm volatile("cp.async.wait_group %0;" :: "n"(N) : "memory"); }

__device__ __forceinline__ void gbar(){
    __threadfence();
    __syncthreads();
    if (threadIdx.x == 0){
        unsigned gen = g_bgen;
        if (atomicAdd(&g_bcnt, 1u) == 127u){
            g_bcnt = 0u;
            __threadfence();
            g_bgen = gen + 1u;
        } else {
            while (g_bgen == gen) __nanosleep(32);
            __threadfence();
        }
    }
    __syncthreads();
}

// ---------- prep: fp32 -> bf16 hi/lo + weight concat ----------
__global__ void prep_k(const float* __restrict__ x, const float* __restrict__ xw,
    const float* __restrict__ w_rx, const float* __restrict__ w_rh, const float* __restrict__ w_re,
    const float* __restrict__ w_zx, const float* __restrict__ w_zh, const float* __restrict__ w_ze,
    const float* __restrict__ w_hx, const float* __restrict__ w_hh,
    const float* __restrict__ w_d,  const float* __restrict__ w_w,  const float* __restrict__ w_m,
    const float* __restrict__ w_t,  const float* __restrict__ w_e)
{
    int i = blockIdx.x*256 + threadIdx.x;
    if (i < M_*I_)  spst(g_x[0],  g_x[1],  i, x[i]);
    if (i < M_*WD_) spst(g_xw[0], g_xw[1], i, xw[i]);
    if (i < B_*H_){ g_h[0][i] = __float2bfloat16(0.f); g_h[1][i] = __float2bfloat16(0.f); }
    if (i < 1024*640){
        int r = i/640, c = i - r*640; float v;
        if (r < 512) v = (c < 128) ? w_rx[r*128+c] : w_re[r*512 + c - 128];
        else { int rr = r-512; v = (c < 128) ? w_zx[rr*128+c] : w_ze[rr*512 + c - 128]; }
        spst(g_Wrz[0], g_Wrz[1], i, v);
    }
    if (i < 512*384){
        int r = i/384, c = i - r*384; int s = c >> 7;
        const float* p = (s==0) ? w_d : (s==1) ? w_w : w_m;
        spst(g_Wo[0], g_Wo[1], i, p[r*128 + (c & 127)]);
    }
    if (i < 512*128) spst(g_Whx[0], g_Whx[1], i, w_hx[i]);
    if (i < 512*512){ spst(g_Wt[0], g_Wt[1], i, w_t[i]); spst(g_Whh[0], g_Whh[1], i, w_hh[i]); }
    if (i < 1024*512){
        int r = i >> 9, c = i & 511;
        spst(g_Wrzh[0], g_Wrzh[1], i, (r < 512) ? w_rh[r*512+c] : w_zh[(r-512)*512+c]);
    }
    if (i < 512*WD_) spst(g_We[0], g_We[1], i, w_e[i]);
}

// ---------- shared HMMA GEMM core: 128x128 tile, K chunks of 64, bf16x3 split ----------
// per stage: Ah[128][72] | Al | Bh[128][72] | Bl   (rows padded to 144B); 2 stages
#define RSTB 144
#define MSZ 18432            // 128*144
#define STG (4*MSZ)          // 73728
#define SMB (2*STG)          // 147456

template<int MODE, int K, int CH>
__device__ __forceinline__ void gemm_tile(const u32 smu, int bm, int bn, int t,
    const float* __restrict__ bias, const float* __restrict__ bias2, float* __restrict__ out)
{
    const int tid = threadIdx.x, lane = tid & 31, wid = tid >> 5;
    const int m0 = (wid >> 1)*32, n0 = (wid & 1)*64;

    const bf16 *BH, *BL;
    if      (MODE==0){ BH=g_We[0];   BL=g_We[1];   }
    else if (MODE==1){ BH=g_Wrz[0];  BL=g_Wrz[1];  }
    else if (MODE==2){ BH=g_Wo[0];   BL=g_Wo[1];   }
    else if (MODE==3){ BH=g_Whx[0];  BL=g_Whx[1];  }
    else if (MODE==4){ BH=g_Wt[0];   BL=g_Wt[1];   }
    else if (MODE==5){ BH=g_Wrzh[0]; BL=g_Wrzh[1]; }
    else             { BH=g_Whh[0];  BL=g_Whh[1];  }

    float acc[2][8][4];
#pragma unroll
    for (int a=0;a<2;a++)
#pragma unroll
        for (int b=0;b<8;b++)
#pragma unroll
            for (int c=0;c<4;c++) acc[a][b][c] = 0.f;

    auto issue = [&](int ch, int st){
        const int k0 = ch*64;
        const u32 sbase = smu + (u32)(st*STG);
#pragma unroll
        for (int it = 0; it < 4; it++){
            int g = tid + it*256;
            int r = g >> 3, kk = k0 + (g & 7)*8;
            int gm = bm + r;
            u32 so = sbase + (u32)(r*RSTB + (g & 7)*16);
            const bf16 *pH = g_x[0], *pL = g_x[1];
            int sz = 16;
            if (MODE == 0){
                if (kk < WD_){ pH = g_xw[0]+gm*WD_+kk; pL = g_xw[1]+gm*WD_+kk; } else sz = 0;
            } else if (MODE == 1){
                if (kk < I_){ pH = g_x[0]+gm*I_+kk; pL = g_x[1]+gm*I_+kk; }
                else        { pH = g_e[0]+gm*H_+kk-I_; pL = g_e[1]+gm*H_+kk-I_; }
            } else if (MODE == 2){
                int seg = kk >> 7, sh = (seg==0) ? 1 : (seg==1) ? 7 : 30;
                int b = gm / T_;
                if (b >= sh){ int s0 = (gm - sh*T_)*I_ + (kk & 127); pH = g_x[0]+s0; pL = g_x[1]+s0; }
                else sz = 0;
            } else if (MODE == 3){ pH = g_x[0]+gm*I_+kk;  pL = g_x[1]+gm*I_+kk; }
            else if (MODE == 4){ pH = g_h[0]+gm*H_+kk;    pL = g_h[1]+gm*H_+kk; }
            else if (MODE == 5){ pH = g_hob[0]+gm*H_+kk;  pL = g_hob[1]+gm*H_+kk; }
            else               { pH = g_ab[0]+gm*H_+kk;   pL = g_ab[1]+gm*H_+kk; }
            cpa(so, pH, sz); cpa(so + MSZ, pL, sz);

            int gn = bn + r;
            int sz2 = (MODE != 0 || kk < WD_) ? 16 : 0;
            const bf16* qH = sz2 ? (BH + gn*K + kk) : BH;
            const bf16* qL = sz2 ? (BL + gn*K + kk) : BL;
            cpa(so + 2*MSZ, qH, sz2); cpa(so + 3*MSZ, qL, sz2);
        }
        cpcommit();
    };

    issue(0, 0);
#pragma unroll 1
    for (int ch = 0; ch < CH; ch++){
        if (ch + 1 < CH){ issue(ch+1, (ch+1)&1); cpwait<1>(); }
        else cpwait<0>();
        __syncthreads();
        const u32 sbase = smu + (u32)((ch&1)*STG);
        const u32 aB = sbase + (u32)((m0 + (lane&7) + ((lane>>3)&1)*8)*RSTB + ((lane>>4)&1)*16);
        const u32 bB = sbase + 2*MSZ + (u32)((n0 + (lane&7) + ((lane>>4)&1)*8)*RSTB + ((lane>>3)&1)*16);
#pragma unroll
        for (int p = 0; p < 3; p++){
            const u32 ab = aB + ((p == 2) ? (u32)MSZ : 0u);
            const u32 bb = bB + ((p == 1) ? (u32)MSZ : 0u);
#pragma unroll
            for (int ks = 0; ks < 4; ks++){
                u32 a0[4], a1[4], bq[4][4];
                ldsm4(a0, ab + ks*32);
                ldsm4(a1, ab + 16*RSTB + ks*32);
#pragma unroll
                for (int nq = 0; nq < 4; nq++) ldsm4(bq[nq], bb + nq*16*RSTB + ks*32);
#pragma unroll
                for (int ni = 0; ni < 8; ni++){
                    const u32* bp = &bq[ni>>1][(ni&1)*2];
                    mmab(acc[0][ni], a0, bp);
                    mmab(acc[1][ni], a1, bp);
                }
            }
        }
        __syncthreads();
    }

    // ---------- epilogue ----------
#pragma unroll
    for (int mi = 0; mi < 2; mi++){
#pragma unroll
        for (int half = 0; half < 2; half++){
            const int gm = bm + m0 + mi*16 + (lane>>2) + half*8;
#pragma unroll
            for (int ni = 0; ni < 8; ni++){
                const int gn = bn + n0 + ni*8 + (lane&3)*2;
                float v0 = acc[mi][ni][half*2+0];
                float v1 = acc[mi][ni][half*2+1];
                if (MODE == 0){
                    spst(g_e[0], g_e[1], gm*H_+gn,   sigf(v0 + bias[gn]));
                    spst(g_e[0], g_e[1], gm*H_+gn+1, sigf(v1 + bias[gn+1]));
                } else if (MODE == 1){
                    int b = gm/T_, tt = gm - b*T_; int base = (tt*B_ + b)*H_;
                    if (gn < H_){
                        g_pre_r[base+gn]   = v0 + bias[gn];
                        g_pre_r[base+gn+1] = v1 + bias[gn+1];
                    } else {
                        g_pre_z[base+gn-H_]   = v0 + bias2[gn-H_];
                        g_pre_z[base+gn-H_+1] = v1 + bias2[gn-H_+1];
                    }
                } else if (MODE == 2){
                    int b = gm/T_, tt = gm - b*T_; int base = (tt*B_ + b)*H_;
                    g_pre_o[base+gn] = v0; g_pre_o[base+gn+1] = v1;
                } else if (MODE == 3){
                    int b = gm/T_, tt = gm - b*T_; int base = (tt*B_ + b)*H_;
                    g_pre_h[base+gn]   = v0 + bias[gn];
                    g_pre_h[base+gn+1] = v1 + bias[gn+1];
                } else if (MODE == 4){
                    int pb = (t*B_ + gm)*H_ + gn, hb = gm*H_ + gn;
                    float h0 = sigf(g_pre_o[pb]   + v0);
                    float h1 = sigf(g_pre_o[pb+1] + v1);
                    g_ho[hb] = h0; g_ho[hb+1] = h1;
                    spst(g_hob[0], g_hob[1], hb,   h0);
                    spst(g_hob[0], g_hob[1], hb+1, h1);
                } else if (MODE == 5){
                    if (gn < H_){
                        int pb = (t*B_ + gm)*H_ + gn, hb = gm*H_ + gn;
                        float r0 = sigf(g_pre_r[pb]   + v0);
                        float r1 = sigf(g_pre_r[pb+1] + v1);
                        spst(g_ab[0], g_ab[1], hb,   r0 * g_ho[hb]);
                        spst(g_ab[0], g_ab[1], hb+1, r1 * g_ho[hb+1]);
                    } else {
                        int n2 = gn - H_;
                        int pb = (t*B_ + gm)*H_ + n2, hb = gm*H_ + n2;
                        g_z[hb]   = sigf(g_pre_z[pb]   + v0);
                        g_z[hb+1] = sigf(g_pre_z[pb+1] + v1);
                    }
                } else {
                    int pb = (t*B_ + gm)*H_ + gn, hb = gm*H_ + gn;
                    float ht0 = tanhf(g_pre_h[pb]   + v0);
                    float ht1 = tanhf(g_pre_h[pb+1] + v1);
                    float z0 = g_z[hb], z1 = g_z[hb+1];
                    float h0 = (1.f - z0)*g_ho[hb]   + z0*ht0;
                    float h1 = (1.f - z1)*g_ho[hb+1] + z1*ht1;
                    spst(g_h[0], g_h[1], hb,   h0);
                    spst(g_h[0], g_h[1], hb+1, h1);
                    out[(gm*T_ + t)*H_ + gn]   = h0;
                    out[(gm*T_ + t)*H_ + gn+1] = h1;
                }
            }
        }
    }
}

// ---------- precompute kernels ----------
template<int MODE, int K, int CH>
__global__ void __launch_bounds__(256)
mm_k(const float* __restrict__ bias, const float* __restrict__ bias2,
     float* __restrict__ out, int t)
{
    extern __shared__ __align__(128) char sm_[];
    gemm_tile<MODE, K, CH>(s2u(sm_), blockIdx.y*128, blockIdx.x*128, t, bias, bias2, out);
}

// ---------- persistent recurrence: grid = 128 CTAs, all 24 steps ----------
__global__ void __launch_bounds__(256)
rec_k(float* __restrict__ out)
{
    extern __shared__ __align__(128) char sm_[];
    const u32 smu = s2u(sm_);
    const int q = blockIdx.x;   // 0..127
#pragma unroll 1
    for (int t = 0; t < T_; t++){
        // R1: 32x4 tiles
        gemm_tile<4,512,8>(smu, (q>>2)*128, (q&3)*128, t, nullptr, nullptr, nullptr);
        gbar();
        // R2: 32x8 tiles, 2 per CTA
        gemm_tile<5,512,8>(smu, (q>>3)*128, (q&7)*128, t, nullptr, nullptr, nullptr);
        gemm_tile<5,512,8>(smu, ((q+128)>>3)*128, ((q+128)&7)*128, t, nullptr, nullptr, nullptr);
        gbar();
        // R3: 32x4 tiles
        gemm_tile<6,512,8>(smu, (q>>2)*128, (q&3)*128, t, nullptr, nullptr, out);
        gbar();
    }
}

// ---------- launcher ----------
extern "C" void kernel_launch(void* const* d_in, const int* in_sizes, int n_in,
                              void* d_out, int out_size)
{
    const float* x    = (const float*)d_in[0];
    const float* xw   = (const float*)d_in[1];
    const float* w_rx = (const float*)d_in[2];
    const float* w_rh = (const float*)d_in[3];
    const float* w_re = (const float*)d_in[4];
    const float* b_r  = (const float*)d_in[5];
    const float* w_zx = (const float*)d_in[6];
    const float* w_zh = (const float*)d_in[7];
    const float* w_ze = (const float*)d_in[8];
    const float* b_z  = (const float*)d_in[9];
    const float* w_hx = (const float*)d_in[10];
    const float* w_hh = (const float*)d_in[11];
    const float* b_h  = (const float*)d_in[12];
    const float* w_d  = (const float*)d_in[13];
    const float* w_w  = (const float*)d_in[14];
    const float* w_m  = (const float*)d_in[15];
    const float* w_t  = (const float*)d_in[16];
    const float* w_e  = (const float*)d_in[17];
    const float* b_e  = (const float*)d_in[18];
    float* out = (float*)d_out;

    cudaFuncSetAttribute(mm_k<0, 32, 1>, cudaFuncAttributeMaxDynamicSharedMemorySize, SMB);
    cudaFuncSetAttribute(mm_k<1,640,10>, cudaFuncAttributeMaxDynamicSharedMemorySize, SMB);
    cudaFuncSetAttribute(mm_k<2,384, 6>, cudaFuncAttributeMaxDynamicSharedMemorySize, SMB);
    cudaFuncSetAttribute(mm_k<3,128, 2>, cudaFuncAttributeMaxDynamicSharedMemorySize, SMB);
    cudaFuncSetAttribute(rec_k,          cudaFuncAttributeMaxDynamicSharedMemorySize, SMB);

    prep_k<<<(M_*I_ + 255)/256, 256>>>(x, xw, w_rx, w_rh, w_re, w_zx, w_zh, w_ze,
                                       w_hx, w_hh, w_d, w_w, w_m, w_t, w_e);

    mm_k<0, 32, 1><<<dim3(4,768), 256, SMB>>>(b_e, nullptr, nullptr, 0);
    mm_k<1,640,10><<<dim3(8,768), 256, SMB>>>(b_r, b_z,    nullptr, 0);
    mm_k<2,384, 6><<<dim3(4,768), 256, SMB>>>(nullptr, nullptr, nullptr, 0);
    mm_k<3,128, 2><<<dim3(4,768), 256, SMB>>>(b_h, nullptr, nullptr, 0);

    rec_k<<<128, 256, SMB>>>(out);
}

// round 7
// speedup vs baseline: 2.0766x; 1.0622x over previous
#include <cuda_runtime.h>
#include <cuda_bf16.h>
#include <cstdint>

#define B_ 4096
#define T_ 24
#define I_ 128
#define H_ 512
#define WD_ 32
#define M_ (B_*T_)

typedef unsigned int u32; typedef unsigned long long u64; typedef __nv_bfloat16 bf16;

// ---------- scratch (device globals; [0]=hi, [1]=lo) ----------
__device__ __align__(16) bf16 g_x[2][M_*I_], g_xw[2][M_*WD_], g_e[2][M_*H_];
__device__ __align__(16) float g_pre_o[M_*H_], g_pre_r[M_*H_], g_pre_z[M_*H_], g_pre_h[M_*H_];
__device__ __align__(16) bf16 g_h[2][B_*H_], g_hob[2][B_*H_], g_ab[2][B_*H_];
__device__ __align__(16) float g_ho[B_*H_], g_z[B_*H_];
__device__ __align__(16) bf16 g_Wrz[2][1024*640], g_Wo[2][512*384], g_Whx[2][512*128];
__device__ __align__(16) bf16 g_Wt[2][512*512], g_Wrzh[2][1024*512], g_Whh[2][512*512], g_We[2][512*WD_];

__device__ unsigned g_bcnt;
__device__ volatile unsigned g_bgen;

__device__ __forceinline__ float sigf(float x){ return 1.f/(1.f + __expf(-x)); }
__device__ __forceinline__ void spst(bf16* hi, bf16* lo, int idx, float v){
    bf16 h = __float2bfloat16(v);
    hi[idx] = h; lo[idx] = __float2bfloat16(v - __bfloat162float(h));
}
__device__ __forceinline__ u32 s2u(const void* p){
    u32 a; asm("{ .reg .u64 t; cvta.to.shared.u64 t, %1; cvt.u32.u64 %0, t; }" : "=r"(a) : "l"(p)); return a;
}
__device__ __forceinline__ void ldsm4(u32* r, u32 addr){
    asm volatile("ldmatrix.sync.aligned.m8n8.x4.shared.b16 {%0,%1,%2,%3}, [%4];"
        : "=r"(r[0]), "=r"(r[1]), "=r"(r[2]), "=r"(r[3]) : "r"(addr));
}
__device__ __forceinline__ void mmab(float* c, const u32* a, const u32* b){
    asm volatile("mma.sync.aligned.m16n8k16.row.col.f32.bf16.bf16.f32 "
        "{%0,%1,%2,%3}, {%4,%5,%6,%7}, {%8,%9}, {%0,%1,%2,%3};"
        : "+f"(c[0]), "+f"(c[1]), "+f"(c[2]), "+f"(c[3])
        : "r"(a[0]), "r"(a[1]), "r"(a[2]), "r"(a[3]), "r"(b[0]), "r"(b[1]));
}
__device__ __forceinline__ void cpa(u32 s, const void* g, int sz){
    asm volatile("cp.async.cg.shared.global [%0], [%1], 16, %2;" :: "r"(s), "l"(g), "r"(sz) : "memory");
}
__device__ __forceinline__ void cpcommit(){ asm volatile("cp.async.commit_group;" ::: "memory"); }
template<int N> __device__ __forceinline__ void cpwait(){ asm volatile("cp.async.wait_group %0;" :: "n"(N) : "memory"); }

__device__ __forceinline__ void gbar(){
    __threadfence();
    __syncthreads();
    if (threadIdx.x == 0){
        unsigned gen = g_bgen;
        if (atomicAdd(&g_bcnt, 1u) == 127u){
            g_bcnt = 0u;
            __threadfence();
            g_bgen = gen + 1u;
        } else {
            while (g_bgen == gen) __nanosleep(32);
            __threadfence();
        }
    }
    __syncthreads();
}

// ---------- prep ----------
__global__ void prep_k(const float* __restrict__ x, const float* __restrict__ xw,
    const float* __restrict__ w_rx, const float* __restrict__ w_rh, const float* __restrict__ w_re,
    const float* __restrict__ w_zx, const float* __restrict__ w_zh, const float* __restrict__ w_ze,
    const float* __restrict__ w_hx, const float* __restrict__ w_hh,
    const float* __restrict__ w_d,  const float* __restrict__ w_w,  const float* __restrict__ w_m,
    const float* __restrict__ w_t,  const float* __restrict__ w_e)
{
    int i = blockIdx.x*256 + threadIdx.x;
    if (i < M_*I_)  spst(g_x[0],  g_x[1],  i, x[i]);
    if (i < M_*WD_) spst(g_xw[0], g_xw[1], i, xw[i]);
    if (i < B_*H_){ g_h[0][i] = __float2bfloat16(0.f); g_h[1][i] = __float2bfloat16(0.f); }
    if (i < 1024*640){
        int r = i/640, c = i - r*640; float v;
        if (r < 512) v = (c < 128) ? w_rx[r*128+c] : w_re[r*512 + c - 128];
        else { int rr = r-512; v = (c < 128) ? w_zx[rr*128+c] : w_ze[rr*512 + c - 128]; }
        spst(g_Wrz[0], g_Wrz[1], i, v);
    }
    if (i < 512*384){
        int r = i/384, c = i - r*384; int s = c >> 7;
        const float* p = (s==0) ? w_d : (s==1) ? w_w : w_m;
        spst(g_Wo[0], g_Wo[1], i, p[r*128 + (c & 127)]);
    }
    if (i < 512*128) spst(g_Whx[0], g_Whx[1], i, w_hx[i]);
    if (i < 512*512){ spst(g_Wt[0], g_Wt[1], i, w_t[i]); spst(g_Whh[0], g_Whh[1], i, w_hh[i]); }
    if (i < 1024*512){
        int r = i >> 9, c = i & 511;
        spst(g_Wrzh[0], g_Wrzh[1], i, (r < 512) ? w_rh[r*512+c] : w_zh[(r-512)*512+c]);
    }
    if (i < 512*WD_) spst(g_We[0], g_We[1], i, w_e[i]);
}

// ---------- HMMA GEMM core: 128x128 tile, K chunks of 64, bf16x3 split, 3-stage pipe ----------
#define RSTB 144
#define MSZ 18432            // 128*144
#define STG (4*MSZ)          // 73728
#define NSTG 3
#define SMB (NSTG*STG)       // 221184

template<int MODE, int K, int CH>
__device__ __forceinline__ void gemm_tile(const u32 smu, int bm, int bn, int t,
    const float* __restrict__ bias, const float* __restrict__ bias2, float* __restrict__ out)
{
    const int tid = threadIdx.x, lane = tid & 31, wid = tid >> 5;
    const int m0 = (wid >> 1)*32, n0 = (wid & 1)*64;

    const bf16 *BH, *BL;
    if      (MODE==0){ BH=g_We[0];   BL=g_We[1];   }
    else if (MODE==1){ BH=g_Wrz[0];  BL=g_Wrz[1];  }
    else if (MODE==2){ BH=g_Wo[0];   BL=g_Wo[1];   }
    else if (MODE==3){ BH=g_Whx[0];  BL=g_Whx[1];  }
    else if (MODE==4){ BH=g_Wt[0];   BL=g_Wt[1];   }
    else if (MODE==5){ BH=g_Wrzh[0]; BL=g_Wrzh[1]; }
    else             { BH=g_Whh[0];  BL=g_Whh[1];  }

    float acc[2][8][4];
#pragma unroll
    for (int a=0;a<2;a++)
#pragma unroll
        for (int b=0;b<8;b++)
#pragma unroll
            for (int c=0;c<4;c++) acc[a][b][c] = 0.f;

    auto issue = [&](int ch){
        const int k0 = ch*64;
        const u32 sbase = smu + (u32)((ch % NSTG)*STG);
#pragma unroll
        for (int it = 0; it < 4; it++){
            int g = tid + it*256;
            int r = g >> 3, kk = k0 + (g & 7)*8;
            int gm = bm + r;
            u32 so = sbase + (u32)(r*RSTB + (g & 7)*16);
            const bf16 *pH = g_x[0], *pL = g_x[1];
            int sz = 16;
            if (MODE == 0){
                if (kk < WD_){ pH = g_xw[0]+gm*WD_+kk; pL = g_xw[1]+gm*WD_+kk; } else sz = 0;
            } else if (MODE == 1){
                if (kk < I_){ pH = g_x[0]+gm*I_+kk; pL = g_x[1]+gm*I_+kk; }
                else        { pH = g_e[0]+gm*H_+kk-I_; pL = g_e[1]+gm*H_+kk-I_; }
            } else if (MODE == 2){
                int seg = kk >> 7, sh = (seg==0) ? 1 : (seg==1) ? 7 : 30;
                int b = gm / T_;
                if (b >= sh){ int s0 = (gm - sh*T_)*I_ + (kk & 127); pH = g_x[0]+s0; pL = g_x[1]+s0; }
                else sz = 0;
            } else if (MODE == 3){ pH = g_x[0]+gm*I_+kk;  pL = g_x[1]+gm*I_+kk; }
            else if (MODE == 4){ pH = g_h[0]+gm*H_+kk;    pL = g_h[1]+gm*H_+kk; }
            else if (MODE == 5){ pH = g_hob[0]+gm*H_+kk;  pL = g_hob[1]+gm*H_+kk; }
            else               { pH = g_ab[0]+gm*H_+kk;   pL = g_ab[1]+gm*H_+kk; }
            cpa(so, pH, sz); cpa(so + MSZ, pL, sz);

            int gn = bn + r;
            int sz2 = (MODE != 0 || kk < WD_) ? 16 : 0;
            const bf16* qH = sz2 ? (BH + gn*K + kk) : BH;
            const bf16* qL = sz2 ? (BL + gn*K + kk) : BL;
            cpa(so + 2*MSZ, qH, sz2); cpa(so + 3*MSZ, qL, sz2);
        }
        cpcommit();
    };

    __syncthreads();            // protect stage buffers across consecutive tiles
    issue(0);
    if (1 < CH) issue(1);

#pragma unroll 1
    for (int ch = 0; ch < CH; ch++){
        if (ch + 1 < CH) cpwait<1>(); else cpwait<0>();
        __syncthreads();
        if (ch + 2 < CH) issue(ch + 2);

        const u32 sbase = smu + (u32)((ch % NSTG)*STG);
        const u32 aB = sbase + (u32)((m0 + (lane&7) + ((lane>>3)&1)*8)*RSTB + ((lane>>4)&1)*16);
        const u32 bB = sbase + 2*MSZ + (u32)((n0 + (lane&7) + ((lane>>4)&1)*8)*RSTB + ((lane>>3)&1)*16);
#pragma unroll
        for (int ks = 0; ks < 4; ks++){
            u32 ah[2][4], al[2][4], bh[4][4], bl[4][4];
            ldsm4(ah[0], aB + ks*32);
            ldsm4(ah[1], aB + 16*RSTB + ks*32);
            ldsm4(al[0], aB + MSZ + ks*32);
            ldsm4(al[1], aB + MSZ + 16*RSTB + ks*32);
#pragma unroll
            for (int nq = 0; nq < 4; nq++){
                ldsm4(bh[nq], bB + nq*16*RSTB + ks*32);
                ldsm4(bl[nq], bB + MSZ + nq*16*RSTB + ks*32);
            }
#pragma unroll
            for (int ni = 0; ni < 8; ni++){
                const u32* ph = &bh[ni>>1][(ni&1)*2];
                const u32* pl = &bl[ni>>1][(ni&1)*2];
                mmab(acc[0][ni], ah[0], ph);
                mmab(acc[1][ni], ah[1], ph);
                mmab(acc[0][ni], ah[0], pl);
                mmab(acc[1][ni], ah[1], pl);
                mmab(acc[0][ni], al[0], ph);
                mmab(acc[1][ni], al[1], ph);
            }
        }
    }

    // ---------- epilogue ----------
#pragma unroll
    for (int mi = 0; mi < 2; mi++){
#pragma unroll
        for (int half = 0; half < 2; half++){
            const int gm = bm + m0 + mi*16 + (lane>>2) + half*8;
#pragma unroll
            for (int ni = 0; ni < 8; ni++){
                const int gn = bn + n0 + ni*8 + (lane&3)*2;
                float v0 = acc[mi][ni][half*2+0];
                float v1 = acc[mi][ni][half*2+1];
                if (MODE == 0){
                    spst(g_e[0], g_e[1], gm*H_+gn,   sigf(v0 + bias[gn]));
                    spst(g_e[0], g_e[1], gm*H_+gn+1, sigf(v1 + bias[gn+1]));
                } else if (MODE == 1){
                    int b = gm/T_, tt = gm - b*T_; int base = (tt*B_ + b)*H_;
                    if (gn < H_){
                        g_pre_r[base+gn]   = v0 + bias[gn];
                        g_pre_r[base+gn+1] = v1 + bias[gn+1];
                    } else {
                        g_pre_z[base+gn-H_]   = v0 + bias2[gn-H_];
                        g_pre_z[base+gn-H_+1] = v1 + bias2[gn-H_+1];
                    }
                } else if (MODE == 2){
                    int b = gm/T_, tt = gm - b*T_; int base = (tt*B_ + b)*H_;
                    g_pre_o[base+gn] = v0; g_pre_o[base+gn+1] = v1;
                } else if (MODE == 3){
                    int b = gm/T_, tt = gm - b*T_; int base = (tt*B_ + b)*H_;
                    g_pre_h[base+gn]   = v0 + bias[gn];
                    g_pre_h[base+gn+1] = v1 + bias[gn+1];
                } else if (MODE == 4){
                    int pb = (t*B_ + gm)*H_ + gn, hb = gm*H_ + gn;
                    float h0 = sigf(g_pre_o[pb]   + v0);
                    float h1 = sigf(g_pre_o[pb+1] + v1);
                    g_ho[hb] = h0; g_ho[hb+1] = h1;
                    spst(g_hob[0], g_hob[1], hb,   h0);
                    spst(g_hob[0], g_hob[1], hb+1, h1);
                } else if (MODE == 5){
                    if (gn < H_){
                        int pb = (t*B_ + gm)*H_ + gn, hb = gm*H_ + gn;
                        float r0 = sigf(g_pre_r[pb]   + v0);
                        float r1 = sigf(g_pre_r[pb+1] + v1);
                        spst(g_ab[0], g_ab[1], hb,   r0 * g_ho[hb]);
                        spst(g_ab[0], g_ab[1], hb+1, r1 * g_ho[hb+1]);
                    } else {
                        int n2 = gn - H_;
                        int pb = (t*B_ + gm)*H_ + n2, hb = gm*H_ + n2;
                        g_z[hb]   = sigf(g_pre_z[pb]   + v0);
                        g_z[hb+1] = sigf(g_pre_z[pb+1] + v1);
                    }
                } else {
                    int pb = (t*B_ + gm)*H_ + gn, hb = gm*H_ + gn;
                    float ht0 = tanhf(g_pre_h[pb]   + v0);
                    float ht1 = tanhf(g_pre_h[pb+1] + v1);
                    float z0 = g_z[hb], z1 = g_z[hb+1];
                    float h0 = (1.f - z0)*g_ho[hb]   + z0*ht0;
                    float h1 = (1.f - z1)*g_ho[hb+1] + z1*ht1;
                    spst(g_h[0], g_h[1], hb,   h0);
                    spst(g_h[0], g_h[1], hb+1, h1);
                    out[(gm*T_ + t)*H_ + gn]   = h0;
                    out[(gm*T_ + t)*H_ + gn+1] = h1;
                }
            }
        }
    }
}

// ---------- precompute kernels ----------
template<int MODE, int K, int CH>
__global__ void __launch_bounds__(256)
mm_k(const float* __restrict__ bias, const float* __restrict__ bias2,
     float* __restrict__ out, int t)
{
    extern __shared__ __align__(128) char sm_[];
    gemm_tile<MODE, K, CH>(s2u(sm_), blockIdx.y*128, blockIdx.x*128, t, bias, bias2, out);
}

// ---------- persistent recurrence ----------
__global__ void __launch_bounds__(256)
rec_k(float* __restrict__ out)
{
    extern __shared__ __align__(128) char sm_[];
    const u32 smu = s2u(sm_);
    const int q = blockIdx.x;   // 0..127
#pragma unroll 1
    for (int t = 0; t < T_; t++){
        gemm_tile<4,512,8>(smu, (q>>2)*128, (q&3)*128, t, nullptr, nullptr, nullptr);
        gbar();
        gemm_tile<5,512,8>(smu, (q>>3)*128, (q&7)*128, t, nullptr, nullptr, nullptr);
        gemm_tile<5,512,8>(smu, ((q+128)>>3)*128, ((q+128)&7)*128, t, nullptr, nullptr, nullptr);
        gbar();
        gemm_tile<6,512,8>(smu, (q>>2)*128, (q&3)*128, t, nullptr, nullptr, out);
        gbar();
    }
}

// ---------- launcher ----------
extern "C" void kernel_launch(void* const* d_in, const int* in_sizes, int n_in,
                              void* d_out, int out_size)
{
    const float* x    = (const float*)d_in[0];
    const float* xw   = (const float*)d_in[1];
    const float* w_rx = (const float*)d_in[2];
    const float* w_rh = (const float*)d_in[3];
    const float* w_re = (const float*)d_in[4];
    const float* b_r  = (const float*)d_in[5];
    const float* w_zx = (const float*)d_in[6];
    const float* w_zh = (const float*)d_in[7];
    const float* w_ze = (const float*)d_in[8];
    const float* b_z  = (const float*)d_in[9];
    const float* w_hx = (const float*)d_in[10];
    const float* w_hh = (const float*)d_in[11];
    const float* b_h  = (const float*)d_in[12];
    const float* w_d  = (const float*)d_in[13];
    const float* w_w  = (const float*)d_in[14];
    const float* w_m  = (const float*)d_in[15];
    const float* w_t  = (const float*)d_in[16];
    const float* w_e  = (const float*)d_in[17];
    const float* b_e  = (const float*)d_in[18];
    float* out = (float*)d_out;

    cudaFuncSetAttribute(mm_k<0, 32, 1>, cudaFuncAttributeMaxDynamicSharedMemorySize, SMB);
    cudaFuncSetAttribute(mm_k<1,640,10>, cudaFuncAttributeMaxDynamicSharedMemorySize, SMB);
    cudaFuncSetAttribute(mm_k<2,384, 6>, cudaFuncAttributeMaxDynamicSharedMemorySize, SMB);
    cudaFuncSetAttribute(mm_k<3,128, 2>, cudaFuncAttributeMaxDynamicSharedMemorySize, SMB);
    cudaFuncSetAttribute(rec_k,          cudaFuncAttributeMaxDynamicSharedMemorySize, SMB);

    prep_k<<<(M_*I_ + 255)/256, 256>>>(x, xw, w_rx, w_rh, w_re, w_zx, w_zh, w_ze,
                                       w_hx, w_hh, w_d, w_w, w_m, w_t, w_e);

    mm_k<0, 32, 1><<<dim3(4,768), 256, SMB>>>(b_e, nullptr, nullptr, 0);
    mm_k<1,640,10><<<dim3(8,768), 256, SMB>>>(b_r, b_z,    nullptr, 0);
    mm_k<2,384, 6><<<dim3(4,768), 256, SMB>>>(nullptr, nullptr, nullptr, 0);
    mm_k<3,128, 2><<<dim3(4,768), 256, SMB>>>(b_h, nullptr, nullptr, 0);

    rec_k<<<128, 256, SMB>>>(out);
}

// round 8
// speedup vs baseline: 2.1757x; 1.0477x over previous
#include <cuda_runtime.h>
#include <cuda_bf16.h>
#include <cstdint>

#define B_ 4096
#define T_ 24
#define I_ 128
#define H_ 512
#define WD_ 32
#define M_ (B_*T_)

typedef unsigned int u32; typedef unsigned long long u64; typedef __nv_bfloat16 bf16;

// ---------- scratch (device globals; [0]=hi, [1]=lo) ----------
__device__ __align__(16) bf16 g_x[2][M_*I_], g_xw[2][M_*WD_], g_e[2][M_*H_];
__device__ __align__(16) float g_pre_o[M_*H_], g_pre_r[M_*H_], g_pre_z[M_*H_], g_pre_h[M_*H_];
__device__ __align__(16) bf16 g_h[2][B_*H_], g_hob[2][B_*H_], g_ab[2][B_*H_];
__device__ __align__(16) float g_ho[B_*H_], g_z[B_*H_];
__device__ __align__(16) bf16 g_Wrz[2][1024*640], g_Wo[2][512*384], g_Whx[2][512*128];
__device__ __align__(16) bf16 g_Wt[2][512*512], g_Wrzh[2][1024*512], g_Whh[2][512*512], g_We[2][512*WD_];

__device__ unsigned g_bcnt;
__device__ volatile unsigned g_bgen;

__device__ __forceinline__ float sigf(float x){ return 1.f/(1.f + __expf(-x)); }
__device__ __forceinline__ void spst(bf16* hi, bf16* lo, int idx, float v){
    bf16 h = __float2bfloat16(v);
    hi[idx] = h; lo[idx] = __float2bfloat16(v - __bfloat162float(h));
}
__device__ __forceinline__ u32 s2u(const void* p){
    u32 a; asm("{ .reg .u64 t; cvta.to.shared.u64 t, %1; cvt.u32.u64 %0, t; }" : "=r"(a) : "l"(p)); return a;
}
__device__ __forceinline__ void ldsm4(u32* r, u32 addr){
    asm volatile("ldmatrix.sync.aligned.m8n8.x4.shared.b16 {%0,%1,%2,%3}, [%4];"
        : "=r"(r[0]), "=r"(r[1]), "=r"(r[2]), "=r"(r[3]) : "r"(addr));
}
__device__ __forceinline__ void mmab(float* c, const u32* a, const u32* b){
    asm volatile("mma.sync.aligned.m16n8k16.row.col.f32.bf16.bf16.f32 "
        "{%0,%1,%2,%3}, {%4,%5,%6,%7}, {%8,%9}, {%0,%1,%2,%3};"
        : "+f"(c[0]), "+f"(c[1]), "+f"(c[2]), "+f"(c[3])
        : "r"(a[0]), "r"(a[1]), "r"(a[2]), "r"(a[3]), "r"(b[0]), "r"(b[1]));
}
__device__ __forceinline__ void cpa(u32 s, const void* g, int sz){
    asm volatile("cp.async.cg.shared.global [%0], [%1], 16, %2;" :: "r"(s), "l"(g), "r"(sz) : "memory");
}
__device__ __forceinline__ void cpcommit(){ asm volatile("cp.async.commit_group;" ::: "memory"); }
template<int N> __device__ __forceinline__ void cpwait(){ asm volatile("cp.async.wait_group %0;" :: "n"(N) : "memory"); }

__device__ __forceinline__ void gbar(){
    __threadfence();
    __syncthreads();
    if (threadIdx.x == 0){
        unsigned gen = g_bgen;
        if (atomicAdd(&g_bcnt, 1u) == 127u){
            g_bcnt = 0u;
            __threadfence();
            g_bgen = gen + 1u;
        } else {
            while (g_bgen == gen) __nanosleep(32);
            __threadfence();
        }
    }
    __syncthreads();
}

// ---------- prep ----------
__global__ void prep_k(const float* __restrict__ x, const float* __restrict__ xw,
    const float* __restrict__ w_rx, const float* __restrict__ w_rh, const float* __restrict__ w_re,
    const float* __restrict__ w_zx, const float* __restrict__ w_zh, const float* __restrict__ w_ze,
    const float* __restrict__ w_hx, const float* __restrict__ w_hh,
    const float* __restrict__ w_d,  const float* __restrict__ w_w,  const float* __restrict__ w_m,
    const float* __restrict__ w_t,  const float* __restrict__ w_e)
{
    int i = blockIdx.x*256 + threadIdx.x;
    if (i < M_*I_)  spst(g_x[0],  g_x[1],  i, x[i]);
    if (i < M_*WD_) spst(g_xw[0], g_xw[1], i, xw[i]);
    if (i < B_*H_){ g_h[0][i] = __float2bfloat16(0.f); g_h[1][i] = __float2bfloat16(0.f); }
    if (i < 1024*640){
        int r = i/640, c = i - r*640; float v;
        if (r < 512) v = (c < 128) ? w_rx[r*128+c] : w_re[r*512 + c - 128];
        else { int rr = r-512; v = (c < 128) ? w_zx[rr*128+c] : w_ze[rr*512 + c - 128]; }
        spst(g_Wrz[0], g_Wrz[1], i, v);
    }
    if (i < 512*384){
        int r = i/384, c = i - r*384; int s = c >> 7;
        const float* p = (s==0) ? w_d : (s==1) ? w_w : w_m;
        spst(g_Wo[0], g_Wo[1], i, p[r*128 + (c & 127)]);
    }
    if (i < 512*128) spst(g_Whx[0], g_Whx[1], i, w_hx[i]);
    if (i < 512*512){ spst(g_Wt[0], g_Wt[1], i, w_t[i]); spst(g_Whh[0], g_Whh[1], i, w_hh[i]); }
    if (i < 1024*512){
        int r = i >> 9, c = i & 511;
        spst(g_Wrzh[0], g_Wrzh[1], i, (r < 512) ? w_rh[r*512+c] : w_zh[(r-512)*512+c]);
    }
    if (i < 512*WD_) spst(g_We[0], g_We[1], i, w_e[i]);
}

// ---------- HMMA GEMM core: 128x128 tile, K chunks of 64, bf16x3 split, 3-stage pipe ----------
#define RSTB 144
#define MSZ 18432            // 128*144
#define STG (4*MSZ)          // 73728
#define NSTG 3
#define SMB (NSTG*STG)       // 221184

template<int MODE, int K, int CH>
__device__ __forceinline__ void gemm_tile(const u32 smu, int bm, int bn, int t,
    const float* __restrict__ bias, const float* __restrict__ bias2, float* __restrict__ out)
{
    const int tid = threadIdx.x, lane = tid & 31, wid = tid >> 5;
    const int m0 = (wid >> 1)*32, n0 = (wid & 1)*64;

    const bf16 *BH, *BL;
    if      (MODE==0){ BH=g_We[0];   BL=g_We[1];   }
    else if (MODE==1){ BH=g_Wrz[0];  BL=g_Wrz[1];  }
    else if (MODE==2){ BH=g_Wo[0];   BL=g_Wo[1];   }
    else if (MODE==3){ BH=g_Whx[0];  BL=g_Whx[1];  }
    else if (MODE==4){ BH=g_Wt[0];   BL=g_Wt[1];   }
    else if (MODE==5){ BH=g_Wrzh[0]; BL=g_Wrzh[1]; }
    else             { BH=g_Whh[0];  BL=g_Whh[1];  }

    float acc[2][8][4];
#pragma unroll
    for (int a=0;a<2;a++)
#pragma unroll
        for (int b=0;b<8;b++)
#pragma unroll
            for (int c=0;c<4;c++) acc[a][b][c] = 0.f;

    auto issue = [&](int ch){
        const int k0 = ch*64;
        const u32 sbase = smu + (u32)((ch % NSTG)*STG);
#pragma unroll
        for (int it = 0; it < 4; it++){
            int g = tid + it*256;
            int r = g >> 3, kk = k0 + (g & 7)*8;
            int gm = bm + r;
            u32 so = sbase + (u32)(r*RSTB + (g & 7)*16);
            const bf16 *pH = g_x[0], *pL = g_x[1];
            int sz = 16;
            if (MODE == 0){
                if (kk < WD_){ pH = g_xw[0]+gm*WD_+kk; pL = g_xw[1]+gm*WD_+kk; } else sz = 0;
            } else if (MODE == 1){
                if (kk < I_){ pH = g_x[0]+gm*I_+kk; pL = g_x[1]+gm*I_+kk; }
                else        { pH = g_e[0]+gm*H_+kk-I_; pL = g_e[1]+gm*H_+kk-I_; }
            } else if (MODE == 2){
                int seg = kk >> 7, sh = (seg==0) ? 1 : (seg==1) ? 7 : 30;
                int b = gm / T_;
                if (b >= sh){ int s0 = (gm - sh*T_)*I_ + (kk & 127); pH = g_x[0]+s0; pL = g_x[1]+s0; }
                else sz = 0;
            } else if (MODE == 3){ pH = g_x[0]+gm*I_+kk;  pL = g_x[1]+gm*I_+kk; }
            else if (MODE == 4){ pH = g_h[0]+gm*H_+kk;    pL = g_h[1]+gm*H_+kk; }
            else if (MODE == 5){ pH = g_hob[0]+gm*H_+kk;  pL = g_hob[1]+gm*H_+kk; }
            else               { pH = g_ab[0]+gm*H_+kk;   pL = g_ab[1]+gm*H_+kk; }
            cpa(so, pH, sz); cpa(so + MSZ, pL, sz);

            int gn = bn + r;
            int sz2 = (MODE != 0 || kk < WD_) ? 16 : 0;
            const bf16* qH = sz2 ? (BH + gn*K + kk) : BH;
            const bf16* qL = sz2 ? (BL + gn*K + kk) : BL;
            cpa(so + 2*MSZ, qH, sz2); cpa(so + 3*MSZ, qL, sz2);
        }
        cpcommit();
    };

    __syncthreads();            // protect stage buffers across consecutive tiles
    issue(0);
    if (1 < CH) issue(1);

#pragma unroll 1
    for (int ch = 0; ch < CH; ch++){
        if (ch + 1 < CH) cpwait<1>(); else cpwait<0>();
        __syncthreads();
        if (ch + 2 < CH) issue(ch + 2);

        const u32 sbase = smu + (u32)((ch % NSTG)*STG);
        const u32 aB = sbase + (u32)((m0 + (lane&7) + ((lane>>3)&1)*8)*RSTB + ((lane>>4)&1)*16);
        const u32 bB = sbase + 2*MSZ + (u32)((n0 + (lane&7) + ((lane>>4)&1)*8)*RSTB + ((lane>>3)&1)*16);
#pragma unroll
        for (int ks = 0; ks < 4; ks++){
            u32 ah[2][4], al[2][4], bh[4][4], bl[4][4];
            ldsm4(ah[0], aB + ks*32);
            ldsm4(ah[1], aB + 16*RSTB + ks*32);
            ldsm4(al[0], aB + MSZ + ks*32);
            ldsm4(al[1], aB + MSZ + 16*RSTB + ks*32);
#pragma unroll
            for (int nq = 0; nq < 4; nq++){
                ldsm4(bh[nq], bB + nq*16*RSTB + ks*32);
                ldsm4(bl[nq], bB + MSZ + nq*16*RSTB + ks*32);
            }
            // product-outermost: same-accumulator reuse distance = 16 MMAs
#pragma unroll
            for (int ni = 0; ni < 8; ni++){
                const u32* ph = &bh[ni>>1][(ni&1)*2];
                mmab(acc[0][ni], ah[0], ph);
                mmab(acc[1][ni], ah[1], ph);
            }
#pragma unroll
            for (int ni = 0; ni < 8; ni++){
                const u32* pl = &bl[ni>>1][(ni&1)*2];
                mmab(acc[0][ni], ah[0], pl);
                mmab(acc[1][ni], ah[1], pl);
            }
#pragma unroll
            for (int ni = 0; ni < 8; ni++){
                const u32* ph = &bh[ni>>1][(ni&1)*2];
                mmab(acc[0][ni], al[0], ph);
                mmab(acc[1][ni], al[1], ph);
            }
        }
    }

    // ---------- epilogue ----------
#pragma unroll
    for (int mi = 0; mi < 2; mi++){
#pragma unroll
        for (int half = 0; half < 2; half++){
            const int gm = bm + m0 + mi*16 + (lane>>2) + half*8;
#pragma unroll
            for (int ni = 0; ni < 8; ni++){
                const int gn = bn + n0 + ni*8 + (lane&3)*2;
                float v0 = acc[mi][ni][half*2+0];
                float v1 = acc[mi][ni][half*2+1];
                if (MODE == 0){
                    spst(g_e[0], g_e[1], gm*H_+gn,   sigf(v0 + bias[gn]));
                    spst(g_e[0], g_e[1], gm*H_+gn+1, sigf(v1 + bias[gn+1]));
                } else if (MODE == 1){
                    int b = gm/T_, tt = gm - b*T_; int base = (tt*B_ + b)*H_;
                    if (gn < H_){
                        g_pre_r[base+gn]   = v0 + bias[gn];
                        g_pre_r[base+gn+1] = v1 + bias[gn+1];
                    } else {
                        g_pre_z[base+gn-H_]   = v0 + bias2[gn-H_];
                        g_pre_z[base+gn-H_+1] = v1 + bias2[gn-H_+1];
                    }
                } else if (MODE == 2){
                    int b = gm/T_, tt = gm - b*T_; int base = (tt*B_ + b)*H_;
                    g_pre_o[base+gn] = v0; g_pre_o[base+gn+1] = v1;
                } else if (MODE == 3){
                    int b = gm/T_, tt = gm - b*T_; int base = (tt*B_ + b)*H_;
                    g_pre_h[base+gn]   = v0 + bias[gn];
                    g_pre_h[base+gn+1] = v1 + bias[gn+1];
                } else if (MODE == 4){
                    int pb = (t*B_ + gm)*H_ + gn, hb = gm*H_ + gn;
                    float h0 = sigf(g_pre_o[pb]   + v0);
                    float h1 = sigf(g_pre_o[pb+1] + v1);
                    g_ho[hb] = h0; g_ho[hb+1] = h1;
                    spst(g_hob[0], g_hob[1], hb,   h0);
                    spst(g_hob[0], g_hob[1], hb+1, h1);
                } else if (MODE == 5){
                    if (gn < H_){
                        int pb = (t*B_ + gm)*H_ + gn, hb = gm*H_ + gn;
                        float r0 = sigf(g_pre_r[pb]   + v0);
                        float r1 = sigf(g_pre_r[pb+1] + v1);
                        spst(g_ab[0], g_ab[1], hb,   r0 * g_ho[hb]);
                        spst(g_ab[0], g_ab[1], hb+1, r1 * g_ho[hb+1]);
                    } else {
                        int n2 = gn - H_;
                        int pb = (t*B_ + gm)*H_ + n2, hb = gm*H_ + n2;
                        g_z[hb]   = sigf(g_pre_z[pb]   + v0);
                        g_z[hb+1] = sigf(g_pre_z[pb+1] + v1);
                    }
                } else {
                    int pb = (t*B_ + gm)*H_ + gn, hb = gm*H_ + gn;
                    float ht0 = tanhf(g_pre_h[pb]   + v0);
                    float ht1 = tanhf(g_pre_h[pb+1] + v1);
                    float z0 = g_z[hb], z1 = g_z[hb+1];
                    float h0 = (1.f - z0)*g_ho[hb]   + z0*ht0;
                    float h1 = (1.f - z1)*g_ho[hb+1] + z1*ht1;
                    spst(g_h[0], g_h[1], hb,   h0);
                    spst(g_h[0], g_h[1], hb+1, h1);
                    out[(gm*T_ + t)*H_ + gn]   = h0;
                    out[(gm*T_ + t)*H_ + gn+1] = h1;
                }
            }
        }
    }
}

// ---------- precompute kernels ----------
template<int MODE, int K, int CH>
__global__ void __launch_bounds__(256)
mm_k(const float* __restrict__ bias, const float* __restrict__ bias2,
     float* __restrict__ out, int t)
{
    extern __shared__ __align__(128) char sm_[];
    gemm_tile<MODE, K, CH>(s2u(sm_), blockIdx.y*128, blockIdx.x*128, t, bias, bias2, out);
}

// ---------- persistent recurrence ----------
__global__ void __launch_bounds__(256)
rec_k(float* __restrict__ out)
{
    extern __shared__ __align__(128) char sm_[];
    const u32 smu = s2u(sm_);
    const int q = blockIdx.x;   // 0..127
#pragma unroll 1
    for (int t = 0; t < T_; t++){
        gemm_tile<4,512,8>(smu, (q>>2)*128, (q&3)*128, t, nullptr, nullptr, nullptr);
        gbar();
        // R2: both tiles share the same A row-block (cols c and c+4)
        gemm_tile<5,512,8>(smu, (q>>2)*128, (q&3)*128,       t, nullptr, nullptr, nullptr);
        gemm_tile<5,512,8>(smu, (q>>2)*128, ((q&3)+4)*128,   t, nullptr, nullptr, nullptr);
        gbar();
        gemm_tile<6,512,8>(smu, (q>>2)*128, (q&3)*128, t, nullptr, nullptr, out);
        gbar();
    }
}

// ---------- launcher ----------
extern "C" void kernel_launch(void* const* d_in, const int* in_sizes, int n_in,
                              void* d_out, int out_size)
{
    const float* x    = (const float*)d_in[0];
    const float* xw   = (const float*)d_in[1];
    const float* w_rx = (const float*)d_in[2];
    const float* w_rh = (const float*)d_in[3];
    const float* w_re = (const float*)d_in[4];
    const float* b_r  = (const float*)d_in[5];
    const float* w_zx = (const float*)d_in[6];
    const float* w_zh = (const float*)d_in[7];
    const float* w_ze = (const float*)d_in[8];
    const float* b_z  = (const float*)d_in[9];
    const float* w_hx = (const float*)d_in[10];
    const float* w_hh = (const float*)d_in[11];
    const float* b_h  = (const float*)d_in[12];
    const float* w_d  = (const float*)d_in[13];
    const float* w_w  = (const float*)d_in[14];
    const float* w_m  = (const float*)d_in[15];
    const float* w_t  = (const float*)d_in[16];
    const float* w_e  = (const float*)d_in[17];
    const float* b_e  = (const float*)d_in[18];
    float* out = (float*)d_out;

    cudaFuncSetAttribute(mm_k<0, 32, 1>, cudaFuncAttributeMaxDynamicSharedMemorySize, SMB);
    cudaFuncSetAttribute(mm_k<1,640,10>, cudaFuncAttributeMaxDynamicSharedMemorySize, SMB);
    cudaFuncSetAttribute(mm_k<2,384, 6>, cudaFuncAttributeMaxDynamicSharedMemorySize, SMB);
    cudaFuncSetAttribute(mm_k<3,128, 2>, cudaFuncAttributeMaxDynamicSharedMemorySize, SMB);
    cudaFuncSetAttribute(rec_k,          cudaFuncAttributeMaxDynamicSharedMemorySize, SMB);

    prep_k<<<(M_*I_ + 255)/256, 256>>>(x, xw, w_rx, w_rh, w_re, w_zx, w_zh, w_ze,
                                       w_hx, w_hh, w_d, w_w, w_m, w_t, w_e);

    mm_k<0, 32, 1><<<dim3(4,768), 256, SMB>>>(b_e, nullptr, nullptr, 0);
    mm_k<1,640,10><<<dim3(8,768), 256, SMB>>>(b_r, b_z,    nullptr, 0);
    mm_k<2,384, 6><<<dim3(4,768), 256, SMB>>>(nullptr, nullptr, nullptr, 0);
    mm_k<3,128, 2><<<dim3(4,768), 256, SMB>>>(b_h, nullptr, nullptr, 0);

    rec_k<<<128, 256, SMB>>>(out);
}

// round 9
// speedup vs baseline: 2.2560x; 1.0369x over previous
#include <cuda_runtime.h>
#include <cuda_bf16.h>
#include <cstdint>

#define B_ 4096
#define T_ 24
#define I_ 128
#define H_ 512
#define WD_ 32
#define M_ (B_*T_)

typedef unsigned int u32; typedef unsigned long long u64; typedef __nv_bfloat16 bf16;

// ---------- scratch (device globals; [0]=hi, [1]=lo) ----------
__device__ __align__(16) bf16 g_x[2][M_*I_], g_xw[2][M_*WD_], g_e[2][M_*H_];
__device__ __align__(16) float g_pre_o[M_*H_], g_pre_r[M_*H_], g_pre_z[M_*H_], g_pre_h[M_*H_];
__device__ __align__(16) bf16 g_h[2][B_*H_], g_hob[2][B_*H_], g_ab[2][B_*H_];
__device__ __align__(16) float g_ho[B_*H_], g_z[B_*H_];
__device__ __align__(16) bf16 g_Wrz[2][1024*640], g_Wo[2][512*384], g_Whx[2][512*128];
__device__ __align__(16) bf16 g_Wt[2][512*512], g_Wrzh[2][1024*512], g_Whh[2][512*512], g_We[2][512*WD_];

__device__ unsigned g_bcnt;
__device__ volatile unsigned g_bgen;

__device__ __forceinline__ float sigf(float x){ return 1.f/(1.f + __expf(-x)); }
__device__ __forceinline__ void spst(bf16* hi, bf16* lo, int idx, float v){
    bf16 h = __float2bfloat16(v);
    hi[idx] = h; lo[idx] = __float2bfloat16(v - __bfloat162float(h));
}
__device__ __forceinline__ u32 s2u(const void* p){
    u32 a; asm("{ .reg .u64 t; cvta.to.shared.u64 t, %1; cvt.u32.u64 %0, t; }" : "=r"(a) : "l"(p)); return a;
}
__device__ __forceinline__ void ldsm4(u32* r, u32 addr){
    asm volatile("ldmatrix.sync.aligned.m8n8.x4.shared.b16 {%0,%1,%2,%3}, [%4];"
        : "=r"(r[0]), "=r"(r[1]), "=r"(r[2]), "=r"(r[3]) : "r"(addr));
}
__device__ __forceinline__ void mmab(float* c, const u32* a, const u32* b){
    asm volatile("mma.sync.aligned.m16n8k16.row.col.f32.bf16.bf16.f32 "
        "{%0,%1,%2,%3}, {%4,%5,%6,%7}, {%8,%9}, {%0,%1,%2,%3};"
        : "+f"(c[0]), "+f"(c[1]), "+f"(c[2]), "+f"(c[3])
        : "r"(a[0]), "r"(a[1]), "r"(a[2]), "r"(a[3]), "r"(b[0]), "r"(b[1]));
}
__device__ __forceinline__ void cpa(u32 s, const void* g, int sz){
    asm volatile("cp.async.cg.shared.global [%0], [%1], 16, %2;" :: "r"(s), "l"(g), "r"(sz) : "memory");
}
__device__ __forceinline__ void cpcommit(){ asm volatile("cp.async.commit_group;" ::: "memory"); }
template<int N> __device__ __forceinline__ void cpwait(){ asm volatile("cp.async.wait_group %0;" :: "n"(N) : "memory"); }

#define NCTA 256
__device__ __forceinline__ void gbar(){
    __threadfence();
    __syncthreads();
    if (threadIdx.x == 0){
        unsigned gen = g_bgen;
        if (atomicAdd(&g_bcnt, 1u) == NCTA-1u){
            g_bcnt = 0u;
            __threadfence();
            g_bgen = gen + 1u;
        } else {
            while (g_bgen == gen) __nanosleep(32);
            __threadfence();
        }
    }
    __syncthreads();
}

// ---------- prep ----------
__global__ void prep_k(const float* __restrict__ x, const float* __restrict__ xw,
    const float* __restrict__ w_rx, const float* __restrict__ w_rh, const float* __restrict__ w_re,
    const float* __restrict__ w_zx, const float* __restrict__ w_zh, const float* __restrict__ w_ze,
    const float* __restrict__ w_hx, const float* __restrict__ w_hh,
    const float* __restrict__ w_d,  const float* __restrict__ w_w,  const float* __restrict__ w_m,
    const float* __restrict__ w_t,  const float* __restrict__ w_e)
{
    int i = blockIdx.x*256 + threadIdx.x;
    if (i < M_*I_)  spst(g_x[0],  g_x[1],  i, x[i]);
    if (i < M_*WD_) spst(g_xw[0], g_xw[1], i, xw[i]);
    if (i < B_*H_){ g_h[0][i] = __float2bfloat16(0.f); g_h[1][i] = __float2bfloat16(0.f); }
    if (i < 1024*640){
        int r = i/640, c = i - r*640; float v;
        if (r < 512) v = (c < 128) ? w_rx[r*128+c] : w_re[r*512 + c - 128];
        else { int rr = r-512; v = (c < 128) ? w_zx[rr*128+c] : w_ze[rr*512 + c - 128]; }
        spst(g_Wrz[0], g_Wrz[1], i, v);
    }
    if (i < 512*384){
        int r = i/384, c = i - r*384; int s = c >> 7;
        const float* p = (s==0) ? w_d : (s==1) ? w_w : w_m;
        spst(g_Wo[0], g_Wo[1], i, p[r*128 + (c & 127)]);
    }
    if (i < 512*128) spst(g_Whx[0], g_Whx[1], i, w_hx[i]);
    if (i < 512*512){ spst(g_Wt[0], g_Wt[1], i, w_t[i]); spst(g_Whh[0], g_Whh[1], i, w_hh[i]); }
    if (i < 1024*512){
        int r = i >> 9, c = i & 511;
        spst(g_Wrzh[0], g_Wrzh[1], i, (r < 512) ? w_rh[r*512+c] : w_zh[(r-512)*512+c]);
    }
    if (i < 512*WD_) spst(g_We[0], g_We[1], i, w_e[i]);
}

// ---------- HMMA GEMM core: 128x128 tile, K chunks of 32, bf16x3 split, 2-stage, 2 CTAs/SM ----------
#define RSTB 80
#define MSZ 10240            // 128*80
#define STG (4*MSZ)          // 40960
#define SMB (2*STG)          // 81920

template<int MODE, int K, int CH>
__device__ __forceinline__ void gemm_tile(const u32 smu, int bm, int bn, int t,
    const float* __restrict__ bias, const float* __restrict__ bias2, float* __restrict__ out)
{
    const int tid = threadIdx.x, lane = tid & 31, wid = tid >> 5;
    const int m0 = (wid >> 1)*32, n0 = (wid & 1)*64;

    const bf16 *BH, *BL;
    if      (MODE==0){ BH=g_We[0];   BL=g_We[1];   }
    else if (MODE==1){ BH=g_Wrz[0];  BL=g_Wrz[1];  }
    else if (MODE==2){ BH=g_Wo[0];   BL=g_Wo[1];   }
    else if (MODE==3){ BH=g_Whx[0];  BL=g_Whx[1];  }
    else if (MODE==4){ BH=g_Wt[0];   BL=g_Wt[1];   }
    else if (MODE==5){ BH=g_Wrzh[0]; BL=g_Wrzh[1]; }
    else             { BH=g_Whh[0];  BL=g_Whh[1];  }

    float acc[2][8][4];
#pragma unroll
    for (int a=0;a<2;a++)
#pragma unroll
        for (int b=0;b<8;b++)
#pragma unroll
            for (int c=0;c<4;c++) acc[a][b][c] = 0.f;

    auto issue = [&](int ch){
        const int k0 = ch*32;
        const u32 sbase = smu + (u32)((ch & 1)*STG);
#pragma unroll
        for (int it = 0; it < 2; it++){
            int g = tid + it*256;
            int r = g >> 2, kk = k0 + (g & 3)*8;
            int gm = bm + r;
            u32 so = sbase + (u32)(r*RSTB + (g & 3)*16);
            const bf16 *pH = g_x[0], *pL = g_x[1];
            int sz = 16;
            if (MODE == 0){
                pH = g_xw[0]+gm*WD_+kk; pL = g_xw[1]+gm*WD_+kk;
            } else if (MODE == 1){
                if (kk < I_){ pH = g_x[0]+gm*I_+kk; pL = g_x[1]+gm*I_+kk; }
                else        { pH = g_e[0]+gm*H_+kk-I_; pL = g_e[1]+gm*H_+kk-I_; }
            } else if (MODE == 2){
                int seg = kk >> 7, sh = (seg==0) ? 1 : (seg==1) ? 7 : 30;
                int b = gm / T_;
                if (b >= sh){ int s0 = (gm - sh*T_)*I_ + (kk & 127); pH = g_x[0]+s0; pL = g_x[1]+s0; }
                else sz = 0;
            } else if (MODE == 3){ pH = g_x[0]+gm*I_+kk;  pL = g_x[1]+gm*I_+kk; }
            else if (MODE == 4){ pH = g_h[0]+gm*H_+kk;    pL = g_h[1]+gm*H_+kk; }
            else if (MODE == 5){ pH = g_hob[0]+gm*H_+kk;  pL = g_hob[1]+gm*H_+kk; }
            else               { pH = g_ab[0]+gm*H_+kk;   pL = g_ab[1]+gm*H_+kk; }
            cpa(so, pH, sz); cpa(so + MSZ, pL, sz);

            int gn = bn + r;
            cpa(so + 2*MSZ, BH + gn*K + kk, 16); cpa(so + 3*MSZ, BL + gn*K + kk, 16);
        }
        cpcommit();
    };

    issue(0);
#pragma unroll 1
    for (int ch = 0; ch < CH; ch++){
        if (ch + 1 < CH){ issue(ch + 1); cpwait<1>(); }
        else cpwait<0>();
        __syncthreads();

        const u32 sbase = smu + (u32)((ch & 1)*STG);
        const u32 aB = sbase + (u32)((m0 + (lane&7) + ((lane>>3)&1)*8)*RSTB + ((lane>>4)&1)*16);
        const u32 bB = sbase + 2*MSZ + (u32)((n0 + (lane&7) + ((lane>>4)&1)*8)*RSTB + ((lane>>3)&1)*16);
#pragma unroll
        for (int ks = 0; ks < 2; ks++){
            u32 ah[2][4], al[2][4], bh[4][4], bl[4][4];
            ldsm4(ah[0], aB + ks*32);
            ldsm4(ah[1], aB + 16*RSTB + ks*32);
            ldsm4(al[0], aB + MSZ + ks*32);
            ldsm4(al[1], aB + MSZ + 16*RSTB + ks*32);
#pragma unroll
            for (int nq = 0; nq < 4; nq++){
                ldsm4(bh[nq], bB + nq*16*RSTB + ks*32);
                ldsm4(bl[nq], bB + MSZ + nq*16*RSTB + ks*32);
            }
#pragma unroll
            for (int ni = 0; ni < 8; ni++){
                const u32* ph = &bh[ni>>1][(ni&1)*2];
                mmab(acc[0][ni], ah[0], ph);
                mmab(acc[1][ni], ah[1], ph);
            }
#pragma unroll
            for (int ni = 0; ni < 8; ni++){
                const u32* pl = &bl[ni>>1][(ni&1)*2];
                mmab(acc[0][ni], ah[0], pl);
                mmab(acc[1][ni], ah[1], pl);
            }
#pragma unroll
            for (int ni = 0; ni < 8; ni++){
                const u32* ph = &bh[ni>>1][(ni&1)*2];
                mmab(acc[0][ni], al[0], ph);
                mmab(acc[1][ni], al[1], ph);
            }
        }
        __syncthreads();   // stage (ch&1) fully consumed before it is re-filled
    }

    // ---------- epilogue ----------
#pragma unroll
    for (int mi = 0; mi < 2; mi++){
#pragma unroll
        for (int half = 0; half < 2; half++){
            const int gm = bm + m0 + mi*16 + (lane>>2) + half*8;
#pragma unroll
            for (int ni = 0; ni < 8; ni++){
                const int gn = bn + n0 + ni*8 + (lane&3)*2;
                float v0 = acc[mi][ni][half*2+0];
                float v1 = acc[mi][ni][half*2+1];
                if (MODE == 0){
                    spst(g_e[0], g_e[1], gm*H_+gn,   sigf(v0 + bias[gn]));
                    spst(g_e[0], g_e[1], gm*H_+gn+1, sigf(v1 + bias[gn+1]));
                } else if (MODE == 1){
                    int b = gm/T_, tt = gm - b*T_; int base = (tt*B_ + b)*H_;
                    if (gn < H_){
                        g_pre_r[base+gn]   = v0 + bias[gn];
                        g_pre_r[base+gn+1] = v1 + bias[gn+1];
                    } else {
                        g_pre_z[base+gn-H_]   = v0 + bias2[gn-H_];
                        g_pre_z[base+gn-H_+1] = v1 + bias2[gn-H_+1];
                    }
                } else if (MODE == 2){
                    int b = gm/T_, tt = gm - b*T_; int base = (tt*B_ + b)*H_;
                    g_pre_o[base+gn] = v0; g_pre_o[base+gn+1] = v1;
                } else if (MODE == 3){
                    int b = gm/T_, tt = gm - b*T_; int base = (tt*B_ + b)*H_;
                    g_pre_h[base+gn]   = v0 + bias[gn];
                    g_pre_h[base+gn+1] = v1 + bias[gn+1];
                } else if (MODE == 4){
                    int pb = (t*B_ + gm)*H_ + gn, hb = gm*H_ + gn;
                    float h0 = sigf(g_pre_o[pb]   + v0);
                    float h1 = sigf(g_pre_o[pb+1] + v1);
                    g_ho[hb] = h0; g_ho[hb+1] = h1;
                    spst(g_hob[0], g_hob[1], hb,   h0);
                    spst(g_hob[0], g_hob[1], hb+1, h1);
                } else if (MODE == 5){
                    if (gn < H_){
                        int pb = (t*B_ + gm)*H_ + gn, hb = gm*H_ + gn;
                        float r0 = sigf(g_pre_r[pb]   + v0);
                        float r1 = sigf(g_pre_r[pb+1] + v1);
                        spst(g_ab[0], g_ab[1], hb,   r0 * g_ho[hb]);
                        spst(g_ab[0], g_ab[1], hb+1, r1 * g_ho[hb+1]);
                    } else {
                        int n2 = gn - H_;
                        int pb = (t*B_ + gm)*H_ + n2, hb = gm*H_ + n2;
                        g_z[hb]   = sigf(g_pre_z[pb]   + v0);
                        g_z[hb+1] = sigf(g_pre_z[pb+1] + v1);
                    }
                } else {
                    int pb = (t*B_ + gm)*H_ + gn, hb = gm*H_ + gn;
                    float ht0 = tanhf(g_pre_h[pb]   + v0);
                    float ht1 = tanhf(g_pre_h[pb+1] + v1);
                    float z0 = g_z[hb], z1 = g_z[hb+1];
                    float h0 = (1.f - z0)*g_ho[hb]   + z0*ht0;
                    float h1 = (1.f - z1)*g_ho[hb+1] + z1*ht1;
                    spst(g_h[0], g_h[1], hb,   h0);
                    spst(g_h[0], g_h[1], hb+1, h1);
                    out[(gm*T_ + t)*H_ + gn]   = h0;
                    out[(gm*T_ + t)*H_ + gn+1] = h1;
                }
            }
        }
    }
}

// ---------- precompute kernels ----------
template<int MODE, int K, int CH>
__global__ void __launch_bounds__(256, 2)
mm_k(const float* __restrict__ bias, const float* __restrict__ bias2,
     float* __restrict__ out, int t)
{
    extern __shared__ __align__(128) char sm_[];
    gemm_tile<MODE, K, CH>(s2u(sm_), blockIdx.y*128, blockIdx.x*128, t, bias, bias2, out);
}

// ---------- persistent recurrence: 256 CTAs (2/SM) ----------
__global__ void __launch_bounds__(256, 2)
rec_k(float* __restrict__ out)
{
    extern __shared__ __align__(128) char sm_[];
    const u32 smu = s2u(sm_);
    const int q = blockIdx.x;   // 0..255
#pragma unroll 1
    for (int t = 0; t < T_; t++){
        if (q < 128)
            gemm_tile<4,512,16>(smu, (q>>2)*128, (q&3)*128, t, nullptr, nullptr, nullptr);
        gbar();
        gemm_tile<5,512,16>(smu, (q>>3)*128, (q&7)*128, t, nullptr, nullptr, nullptr);
        gbar();
        if (q < 128)
            gemm_tile<6,512,16>(smu, (q>>2)*128, (q&3)*128, t, nullptr, nullptr, out);
        gbar();
    }
}

// ---------- launcher ----------
extern "C" void kernel_launch(void* const* d_in, const int* in_sizes, int n_in,
                              void* d_out, int out_size)
{
    const float* x    = (const float*)d_in[0];
    const float* xw   = (const float*)d_in[1];
    const float* w_rx = (const float*)d_in[2];
    const float* w_rh = (const float*)d_in[3];
    const float* w_re = (const float*)d_in[4];
    const float* b_r  = (const float*)d_in[5];
    const float* w_zx = (const float*)d_in[6];
    const float* w_zh = (const float*)d_in[7];
    const float* w_ze = (const float*)d_in[8];
    const float* b_z  = (const float*)d_in[9];
    const float* w_hx = (const float*)d_in[10];
    const float* w_hh = (const float*)d_in[11];
    const float* b_h  = (const float*)d_in[12];
    const float* w_d  = (const float*)d_in[13];
    const float* w_w  = (const float*)d_in[14];
    const float* w_m  = (const float*)d_in[15];
    const float* w_t  = (const float*)d_in[16];
    const float* w_e  = (const float*)d_in[17];
    const float* b_e  = (const float*)d_in[18];
    float* out = (float*)d_out;

    cudaFuncSetAttribute(mm_k<0, 32, 1>, cudaFuncAttributeMaxDynamicSharedMemorySize, SMB);
    cudaFuncSetAttribute(mm_k<1,640,20>, cudaFuncAttributeMaxDynamicSharedMemorySize, SMB);
    cudaFuncSetAttribute(mm_k<2,384,12>, cudaFuncAttributeMaxDynamicSharedMemorySize, SMB);
    cudaFuncSetAttribute(mm_k<3,128, 4>, cudaFuncAttributeMaxDynamicSharedMemorySize, SMB);
    cudaFuncSetAttribute(rec_k,          cudaFuncAttributeMaxDynamicSharedMemorySize, SMB);

    prep_k<<<(M_*I_ + 255)/256, 256>>>(x, xw, w_rx, w_rh, w_re, w_zx, w_zh, w_ze,
                                       w_hx, w_hh, w_d, w_w, w_m, w_t, w_e);

    mm_k<0, 32, 1><<<dim3(4,768), 256, SMB>>>(b_e, nullptr, nullptr, 0);
    mm_k<1,640,20><<<dim3(8,768), 256, SMB>>>(b_r, b_z,    nullptr, 0);
    mm_k<2,384,12><<<dim3(4,768), 256, SMB>>>(nullptr, nullptr, nullptr, 0);
    mm_k<3,128, 4><<<dim3(4,768), 256, SMB>>>(b_h, nullptr, nullptr, 0);

    rec_k<<<NCTA, 256, SMB>>>(out);
}

// round 11
// speedup vs baseline: 2.3922x; 1.0604x over previous
#include <cuda_runtime.h>
#include <cuda_bf16.h>
#include <cstdint>

#define B_ 4096
#define T_ 24
#define I_ 128
#define H_ 512
#define WD_ 32
#define M_ (B_*T_)

typedef unsigned int u32; typedef unsigned long long u64; typedef __nv_bfloat16 bf16;

// ---------- scratch (device globals; [0]=hi, [1]=lo) ----------
__device__ __align__(16) bf16 g_x[2][M_*I_], g_xw[2][M_*WD_], g_e[2][M_*H_];
__device__ __align__(16) float g_pre_o[M_*H_], g_pre_r[M_*H_], g_pre_z[M_*H_], g_pre_h[M_*H_];
__device__ __align__(16) bf16 g_h[2][B_*H_], g_hob[2][B_*H_], g_ab[2][B_*H_];
__device__ __align__(16) float g_ho[B_*H_], g_z[B_*H_];
__device__ __align__(16) bf16 g_Wrz[2][1024*640], g_Wo[2][512*384], g_Whx[2][512*128];
__device__ __align__(16) bf16 g_Wt[2][512*512], g_Wrzh[2][1024*512], g_Whh[2][512*512], g_We[2][512*WD_];

__device__ unsigned g_bcnt;
__device__ volatile unsigned g_bgen;

__device__ __forceinline__ float sigf(float x){ return 1.f/(1.f + __expf(-x)); }
__device__ __forceinline__ void spst(bf16* hi, bf16* lo, int idx, float v){
    bf16 h = __float2bfloat16(v);
    hi[idx] = h; lo[idx] = __float2bfloat16(v - __bfloat162float(h));
}
__device__ __forceinline__ u32 s2u(const void* p){
    u32 a; asm("{ .reg .u64 t; cvta.to.shared.u64 t, %1; cvt.u32.u64 %0, t; }" : "=r"(a) : "l"(p)); return a;
}
__device__ __forceinline__ void ldsm4(u32* r, u32 addr){
    asm volatile("ldmatrix.sync.aligned.m8n8.x4.shared.b16 {%0,%1,%2,%3}, [%4];"
        : "=r"(r[0]), "=r"(r[1]), "=r"(r[2]), "=r"(r[3]) : "r"(addr));
}
__device__ __forceinline__ void mmab(float* c, const u32* a, const u32* b){
    asm volatile("mma.sync.aligned.m16n8k16.row.col.f32.bf16.bf16.f32 "
        "{%0,%1,%2,%3}, {%4,%5,%6,%7}, {%8,%9}, {%0,%1,%2,%3};"
        : "+f"(c[0]), "+f"(c[1]), "+f"(c[2]), "+f"(c[3])
        : "r"(a[0]), "r"(a[1]), "r"(a[2]), "r"(a[3]), "r"(b[0]), "r"(b[1]));
}
__device__ __forceinline__ void cpa(u32 s, const void* g, int sz){
    asm volatile("cp.async.cg.shared.global [%0], [%1], 16, %2;" :: "r"(s), "l"(g), "r"(sz) : "memory");
}
__device__ __forceinline__ void cpcommit(){ asm volatile("cp.async.commit_group;" ::: "memory"); }
template<int N> __device__ __forceinline__ void cpwait(){ asm volatile("cp.async.wait_group %0;" :: "n"(N) : "memory"); }

#define NCTA 256
__device__ __forceinline__ void gbar(){
    __threadfence();
    __syncthreads();
    if (threadIdx.x == 0){
        unsigned gen = g_bgen;
        if (atomicAdd(&g_bcnt, 1u) == NCTA-1u){
            g_bcnt = 0u;
            __threadfence();
            g_bgen = gen + 1u;
        } else {
            while (g_bgen == gen) __nanosleep(32);
            __threadfence();
        }
    }
    __syncthreads();
}

// ---------- prep ----------
__global__ void prep_k(const float* __restrict__ x, const float* __restrict__ xw,
    const float* __restrict__ w_rx, const float* __restrict__ w_rh, const float* __restrict__ w_re,
    const float* __restrict__ w_zx, const float* __restrict__ w_zh, const float* __restrict__ w_ze,
    const float* __restrict__ w_hx, const float* __restrict__ w_hh,
    const float* __restrict__ w_d,  const float* __restrict__ w_w,  const float* __restrict__ w_m,
    const float* __restrict__ w_t,  const float* __restrict__ w_e)
{
    int i = blockIdx.x*256 + threadIdx.x;
    if (i < M_*I_)  spst(g_x[0],  g_x[1],  i, x[i]);
    if (i < M_*WD_) spst(g_xw[0], g_xw[1], i, xw[i]);
    if (i < B_*H_){ g_h[0][i] = __float2bfloat16(0.f); g_h[1][i] = __float2bfloat16(0.f); }
    if (i < 1024*640){
        int r = i/640, c = i - r*640; float v;
        if (r < 512) v = (c < 128) ? w_rx[r*128+c] : w_re[r*512 + c - 128];
        else { int rr = r-512; v = (c < 128) ? w_zx[rr*128+c] : w_ze[rr*512 + c - 128]; }
        spst(g_Wrz[0], g_Wrz[1], i, v);
    }
    if (i < 512*384){
        int r = i/384, c = i - r*384; int s = c >> 7;
        const float* p = (s==0) ? w_d : (s==1) ? w_w : w_m;
        spst(g_Wo[0], g_Wo[1], i, p[r*128 + (c & 127)]);
    }
    if (i < 512*128) spst(g_Whx[0], g_Whx[1], i, w_hx[i]);
    if (i < 512*512){ spst(g_Wt[0], g_Wt[1], i, w_t[i]); spst(g_Whh[0], g_Whh[1], i, w_hh[i]); }
    if (i < 1024*512){
        int r = i >> 9, c = i & 511;
        spst(g_Wrzh[0], g_Wrzh[1], i, (r < 512) ? w_rh[r*512+c] : w_zh[(r-512)*512+c]);
    }
    if (i < 512*WD_) spst(g_We[0], g_We[1], i, w_e[i]);
}

// ---------- HMMA GEMM core: 128xBN tile, K chunks of 32, bf16x3 split, 2-stage ----------
#define RSTB 80
#define MSZ 10240            // 128*80
#define STG (4*MSZ)          // 40960
#define SMB (2*STG)          // 81920

template<int MODE, int K, int CH, int BN>
__device__ __forceinline__ void gemm_tile(const u32 smu, int bm, int bn, int t,
    const float* __restrict__ bias, const float* __restrict__ bias2, float* __restrict__ out)
{
    const int tid = threadIdx.x, lane = tid & 31, wid = tid >> 5;
    constexpr int MI = (BN == 128) ? 2 : 1;
    const int m0 = (BN == 128) ? (wid >> 1)*32 : wid*16;
    const int n0 = (BN == 128) ? (wid & 1)*64 : 0;

    const bf16 *BH, *BL;
    if      (MODE==0){ BH=g_We[0];   BL=g_We[1];   }
    else if (MODE==1){ BH=g_Wrz[0];  BL=g_Wrz[1];  }
    else if (MODE==2){ BH=g_Wo[0];   BL=g_Wo[1];   }
    else if (MODE==3){ BH=g_Whx[0];  BL=g_Whx[1];  }
    else if (MODE==4){ BH=g_Wt[0];   BL=g_Wt[1];   }
    else if (MODE==5){ BH=g_Wrzh[0]; BL=g_Wrzh[1]; }
    else             { BH=g_Whh[0];  BL=g_Whh[1];  }

    float acc[MI][8][4];
#pragma unroll
    for (int a=0;a<MI;a++)
#pragma unroll
        for (int b=0;b<8;b++)
#pragma unroll
            for (int c=0;c<4;c++) acc[a][b][c] = 0.f;

    auto issue = [&](int ch){
        const int k0 = ch*32;
        const u32 sbase = smu + (u32)((ch & 1)*STG);
#pragma unroll
        for (int it = 0; it < 2; it++){
            int g = tid + it*256;
            int r = g >> 2, kk = k0 + (g & 3)*8;
            int gm = bm + r;
            u32 so = sbase + (u32)(r*RSTB + (g & 3)*16);
            const bf16 *pH = g_x[0], *pL = g_x[1];
            int sz = 16;
            if (MODE == 0){
                pH = g_xw[0]+gm*WD_+kk; pL = g_xw[1]+gm*WD_+kk;
            } else if (MODE == 1){
                if (kk < I_){ pH = g_x[0]+gm*I_+kk; pL = g_x[1]+gm*I_+kk; }
                else        { pH = g_e[0]+gm*H_+kk-I_; pL = g_e[1]+gm*H_+kk-I_; }
            } else if (MODE == 2){
                int seg = kk >> 7, sh = (seg==0) ? 1 : (seg==1) ? 7 : 30;
                int b = gm / T_;
                if (b >= sh){ int s0 = (gm - sh*T_)*I_ + (kk & 127); pH = g_x[0]+s0; pL = g_x[1]+s0; }
                else sz = 0;
            } else if (MODE == 3){ pH = g_x[0]+gm*I_+kk;  pL = g_x[1]+gm*I_+kk; }
            else if (MODE == 4){ pH = g_h[0]+gm*H_+kk;    pL = g_h[1]+gm*H_+kk; }
            else if (MODE == 5){ pH = g_hob[0]+gm*H_+kk;  pL = g_hob[1]+gm*H_+kk; }
            else               { pH = g_ab[0]+gm*H_+kk;   pL = g_ab[1]+gm*H_+kk; }
            cpa(so, pH, sz); cpa(so + MSZ, pL, sz);

            if (r < BN){
                int gn = bn + r;
                cpa(so + 2*MSZ, BH + gn*K + kk, 16); cpa(so + 3*MSZ, BL + gn*K + kk, 16);
            }
        }
        cpcommit();
    };

    issue(0);
#pragma unroll 1
    for (int ch = 0; ch < CH; ch++){
        if (ch + 1 < CH){ issue(ch + 1); cpwait<1>(); }
        else cpwait<0>();
        __syncthreads();

        const u32 sbase = smu + (u32)((ch & 1)*STG);
        const u32 aB = sbase + (u32)((m0 + (lane&7) + ((lane>>3)&1)*8)*RSTB + ((lane>>4)&1)*16);
        const u32 bB = sbase + 2*MSZ + (u32)((n0 + (lane&7) + ((lane>>4)&1)*8)*RSTB + ((lane>>3)&1)*16);
#pragma unroll
        for (int ks = 0; ks < 2; ks++){
            u32 ah[MI][4], al[MI][4], bh[4][4], bl[4][4];
            ldsm4(ah[0], aB + ks*32);
            ldsm4(al[0], aB + MSZ + ks*32);
            if (MI == 2){
                ldsm4(ah[1], aB + 16*RSTB + ks*32);
                ldsm4(al[1], aB + MSZ + 16*RSTB + ks*32);
            }
#pragma unroll
            for (int nq = 0; nq < 4; nq++){
                ldsm4(bh[nq], bB + nq*16*RSTB + ks*32);
                ldsm4(bl[nq], bB + MSZ + nq*16*RSTB + ks*32);
            }
#pragma unroll
            for (int ni = 0; ni < 8; ni++){
                const u32* ph = &bh[ni>>1][(ni&1)*2];
                mmab(acc[0][ni], ah[0], ph);
                if (MI == 2) mmab(acc[1][ni], ah[1], ph);
            }
#pragma unroll
            for (int ni = 0; ni < 8; ni++){
                const u32* pl = &bl[ni>>1][(ni&1)*2];
                mmab(acc[0][ni], ah[0], pl);
                if (MI == 2) mmab(acc[1][ni], ah[1], pl);
            }
#pragma unroll
            for (int ni = 0; ni < 8; ni++){
                const u32* ph = &bh[ni>>1][(ni&1)*2];
                mmab(acc[0][ni], al[0], ph);
                if (MI == 2) mmab(acc[1][ni], al[1], ph);
            }
        }
        __syncthreads();   // stage (ch&1) fully consumed before re-fill
    }

    // ---------- epilogue ----------
#pragma unroll
    for (int mi = 0; mi < MI; mi++){
#pragma unroll
        for (int half = 0; half < 2; half++){
            const int gm = bm + m0 + mi*16 + (lane>>2) + half*8;
#pragma unroll
            for (int ni = 0; ni < 8; ni++){
                const int gn = bn + n0 + ni*8 + (lane&3)*2;
                float v0 = acc[mi][ni][half*2+0];
                float v1 = acc[mi][ni][half*2+1];
                if (MODE == 0){
                    spst(g_e[0], g_e[1], gm*H_+gn,   sigf(v0 + bias[gn]));
                    spst(g_e[0], g_e[1], gm*H_+gn+1, sigf(v1 + bias[gn+1]));
                } else if (MODE == 1){
                    int b = gm/T_, tt = gm - b*T_; int base = (tt*B_ + b)*H_;
                    if (gn < H_){
                        g_pre_r[base+gn]   = v0 + bias[gn];
                        g_pre_r[base+gn+1] = v1 + bias[gn+1];
                    } else {
                        g_pre_z[base+gn-H_]   = v0 + bias2[gn-H_];
                        g_pre_z[base+gn-H_+1] = v1 + bias2[gn-H_+1];
                    }
                } else if (MODE == 2){
                    int b = gm/T_, tt = gm - b*T_; int base = (tt*B_ + b)*H_;
                    g_pre_o[base+gn] = v0; g_pre_o[base+gn+1] = v1;
                } else if (MODE == 3){
                    int b = gm/T_, tt = gm - b*T_; int base = (tt*B_ + b)*H_;
                    g_pre_h[base+gn]   = v0 + bias[gn];
                    g_pre_h[base+gn+1] = v1 + bias[gn+1];
                } else if (MODE == 4){
                    int pb = (t*B_ + gm)*H_ + gn, hb = gm*H_ + gn;
                    float h0 = sigf(g_pre_o[pb]   + v0);
                    float h1 = sigf(g_pre_o[pb+1] + v1);
                    g_ho[hb] = h0; g_ho[hb+1] = h1;
                    spst(g_hob[0], g_hob[1], hb,   h0);
                    spst(g_hob[0], g_hob[1], hb+1, h1);
                } else if (MODE == 5){
                    if (gn < H_){
                        int pb = (t*B_ + gm)*H_ + gn, hb = gm*H_ + gn;
                        float r0 = sigf(g_pre_r[pb]   + v0);
                        float r1 = sigf(g_pre_r[pb+1] + v1);
                        spst(g_ab[0], g_ab[1], hb,   r0 * g_ho[hb]);
                        spst(g_ab[0], g_ab[1], hb+1, r1 * g_ho[hb+1]);
                    } else {
                        int n2 = gn - H_;
                        int pb = (t*B_ + gm)*H_ + n2, hb = gm*H_ + n2;
                        g_z[hb]   = sigf(g_pre_z[pb]   + v0);
                        g_z[hb+1] = sigf(g_pre_z[pb+1] + v1);
                    }
                } else {
                    int pb = (t*B_ + gm)*H_ + gn, hb = gm*H_ + gn;
                    float ht0 = tanhf(g_pre_h[pb]   + v0);
                    float ht1 = tanhf(g_pre_h[pb+1] + v1);
                    float z0 = g_z[hb], z1 = g_z[hb+1];
                    float h0 = (1.f - z0)*g_ho[hb]   + z0*ht0;
                    float h1 = (1.f - z1)*g_ho[hb+1] + z1*ht1;
                    spst(g_h[0], g_h[1], hb,   h0);
                    spst(g_h[0], g_h[1], hb+1, h1);
                    out[(gm*T_ + t)*H_ + gn]   = h0;
                    out[(gm*T_ + t)*H_ + gn+1] = h1;
                }
            }
        }
    }
}

// ---------- precompute kernels ----------
template<int MODE, int K, int CH>
__global__ void __launch_bounds__(256, 2)
mm_k(const float* __restrict__ bias, const float* __restrict__ bias2,
     float* __restrict__ out, int t)
{
    extern __shared__ __align__(128) char sm_[];
    gemm_tile<MODE, K, CH, 128>(s2u(sm_), blockIdx.y*128, blockIdx.x*128, t, bias, bias2, out);
}

// ---------- persistent recurrence: 256 CTAs (2/SM), all phases full-width ----------
__global__ void __launch_bounds__(256, 2)
rec_k(float* __restrict__ out)
{
    extern __shared__ __align__(128) char sm_[];
    const u32 smu = s2u(sm_);
    const int q = blockIdx.x;   // 0..255
    const int bm = (q >> 3)*128;
#pragma unroll 1
    for (int t = 0; t < T_; t++){
        gemm_tile<4,512,16, 64>(smu, bm, (q&7)*64,  t, nullptr, nullptr, nullptr);
        gbar();
        gemm_tile<5,512,16,128>(smu, bm, (q&7)*128, t, nullptr, nullptr, nullptr);
        gbar();
        gemm_tile<6,512,16, 64>(smu, bm, (q&7)*64,  t, nullptr, nullptr, out);
        gbar();
    }
}

// ---------- launcher ----------
extern "C" void kernel_launch(void* const* d_in, const int* in_sizes, int n_in,
                              void* d_out, int out_size)
{
    const float* x    = (const float*)d_in[0];
    const float* xw   = (const float*)d_in[1];
    const float* w_rx = (const float*)d_in[2];
    const float* w_rh = (const float*)d_in[3];
    const float* w_re = (const float*)d_in[4];
    const float* b_r  = (const float*)d_in[5];
    const float* w_zx = (const float*)d_in[6];
    const float* w_zh = (const float*)d_in[7];
    const float* w_ze = (const float*)d_in[8];
    const float* b_z  = (const float*)d_in[9];
    const float* w_hx = (const float*)d_in[10];
    const float* w_hh = (const float*)d_in[11];
    const float* b_h  = (const float*)d_in[12];
    const float* w_d  = (const float*)d_in[13];
    const float* w_w  = (const float*)d_in[14];
    const float* w_m  = (const float*)d_in[15];
    const float* w_t  = (const float*)d_in[16];
    const float* w_e  = (const float*)d_in[17];
    const float* b_e  = (const float*)d_in[18];
    float* out = (float*)d_out;

    cudaFuncSetAttribute(mm_k<0, 32, 1>, cudaFuncAttributeMaxDynamicSharedMemorySize, SMB);
    cudaFuncSetAttribute(mm_k<1,640,20>, cudaFuncAttributeMaxDynamicSharedMemorySize, SMB);
    cudaFuncSetAttribute(mm_k<2,384,12>, cudaFuncAttributeMaxDynamicSharedMemorySize, SMB);
    cudaFuncSetAttribute(mm_k<3,128, 4>, cudaFuncAttributeMaxDynamicSharedMemorySize, SMB);
    cudaFuncSetAttribute(rec_k,          cudaFuncAttributeMaxDynamicSharedMemorySize, SMB);

    prep_k<<<(M_*I_ + 255)/256, 256>>>(x, xw, w_rx, w_rh, w_re, w_zx, w_zh, w_ze,
                                       w_hx, w_hh, w_d, w_w, w_m, w_t, w_e);

    mm_k<0, 32, 1><<<dim3(4,768), 256, SMB>>>(b_e, nullptr, nullptr, 0);
    mm_k<1,640,20><<<dim3(8,768), 256, SMB>>>(b_r, b_z,    nullptr, 0);
    mm_k<2,384,12><<<dim3(4,768), 256, SMB>>>(nullptr, nullptr, nullptr, 0);
    mm_k<3,128, 4><<<dim3(4,768), 256, SMB>>>(b_h, nullptr, nullptr, 0);

    rec_k<<<NCTA, 256, SMB>>>(out);
}

// round 12
// speedup vs baseline: 2.6609x; 1.1123x over previous
#include <cuda_runtime.h>
#include <cuda_bf16.h>
#include <cstdint>

#define B_ 4096
#define T_ 24
#define I_ 128
#define H_ 512
#define WD_ 32
#define M_ (B_*T_)

typedef unsigned int u32; typedef unsigned long long u64; typedef __nv_bfloat16 bf16;

// ---------- scratch (device globals; [0]=hi, [1]=lo) ----------
__device__ __align__(16) bf16 g_x[2][M_*I_], g_xw[2][M_*WD_], g_e[2][M_*H_];
__device__ __align__(16) float g_pre_o[M_*H_], g_pre_r[M_*H_], g_pre_z[M_*H_], g_pre_h[M_*H_];
__device__ __align__(16) bf16 g_h[2][B_*H_], g_hob[2][B_*H_], g_ab[2][B_*H_];
__device__ __align__(16) float g_ho[B_*H_], g_z[B_*H_];
__device__ __align__(16) bf16 g_Wrz[2][1024*640], g_Wo[2][512*384], g_Whx[2][512*128];
__device__ __align__(16) bf16 g_Wt[2][512*512], g_Wrzh[2][1024*512], g_Whh[2][512*512], g_We[2][512*WD_];

__device__ unsigned g_bcnt;
__device__ volatile unsigned g_bgen;

__device__ __forceinline__ float sigf(float x){ return 1.f/(1.f + __expf(-x)); }
__device__ __forceinline__ void spst(bf16* hi, bf16* lo, int idx, float v){
    bf16 h = __float2bfloat16(v);
    hi[idx] = h; lo[idx] = __float2bfloat16(v - __bfloat162float(h));
}
__device__ __forceinline__ u32 s2u(const void* p){
    u32 a; asm("{ .reg .u64 t; cvta.to.shared.u64 t, %1; cvt.u32.u64 %0, t; }" : "=r"(a) : "l"(p)); return a;
}
__device__ __forceinline__ void ldsm4(u32* r, u32 addr){
    asm volatile("ldmatrix.sync.aligned.m8n8.x4.shared.b16 {%0,%1,%2,%3}, [%4];"
        : "=r"(r[0]), "=r"(r[1]), "=r"(r[2]), "=r"(r[3]) : "r"(addr));
}
__device__ __forceinline__ void mmab(float* c, const u32* a, const u32* b){
    asm volatile("mma.sync.aligned.m16n8k16.row.col.f32.bf16.bf16.f32 "
        "{%0,%1,%2,%3}, {%4,%5,%6,%7}, {%8,%9}, {%0,%1,%2,%3};"
        : "+f"(c[0]), "+f"(c[1]), "+f"(c[2]), "+f"(c[3])
        : "r"(a[0]), "r"(a[1]), "r"(a[2]), "r"(a[3]), "r"(b[0]), "r"(b[1]));
}
__device__ __forceinline__ void cpa(u32 s, const void* g, int sz){
    asm volatile("cp.async.cg.shared.global [%0], [%1], 16, %2;" :: "r"(s), "l"(g), "r"(sz) : "memory");
}
__device__ __forceinline__ void cpcommit(){ asm volatile("cp.async.commit_group;" ::: "memory"); }
template<int N> __device__ __forceinline__ void cpwait(){ asm volatile("cp.async.wait_group %0;" :: "n"(N) : "memory"); }

#define NCTA 256
__device__ __forceinline__ void gbar(){
    __threadfence();
    __syncthreads();
    if (threadIdx.x == 0){
        unsigned gen = g_bgen;
        if (atomicAdd(&g_bcnt, 1u) == NCTA-1u){
            g_bcnt = 0u;
            __threadfence();
            g_bgen = gen + 1u;
        } else {
            while (g_bgen == gen) __nanosleep(32);
            __threadfence();
        }
    }
    __syncthreads();
}

// ---------- prep ----------
__global__ void prep_k(const float* __restrict__ x, const float* __restrict__ xw,
    const float* __restrict__ w_rx, const float* __restrict__ w_rh, const float* __restrict__ w_re,
    const float* __restrict__ w_zx, const float* __restrict__ w_zh, const float* __restrict__ w_ze,
    const float* __restrict__ w_hx, const float* __restrict__ w_hh,
    const float* __restrict__ w_d,  const float* __restrict__ w_w,  const float* __restrict__ w_m,
    const float* __restrict__ w_t,  const float* __restrict__ w_e)
{
    int i = blockIdx.x*256 + threadIdx.x;
    if (i < M_*I_)  spst(g_x[0],  g_x[1],  i, x[i]);
    if (i < M_*WD_) spst(g_xw[0], g_xw[1], i, xw[i]);
    if (i < B_*H_){ g_h[0][i] = __float2bfloat16(0.f); g_h[1][i] = __float2bfloat16(0.f); }
    if (i < 1024*640){
        int r = i/640, c = i - r*640; float v;
        if (r < 512) v = (c < 128) ? w_rx[r*128+c] : w_re[r*512 + c - 128];
        else { int rr = r-512; v = (c < 128) ? w_zx[rr*128+c] : w_ze[rr*512 + c - 128]; }
        spst(g_Wrz[0], g_Wrz[1], i, v);
    }
    if (i < 512*384){
        int r = i/384, c = i - r*384; int s = c >> 7;
        const float* p = (s==0) ? w_d : (s==1) ? w_w : w_m;
        spst(g_Wo[0], g_Wo[1], i, p[r*128 + (c & 127)]);
    }
    if (i < 512*128) spst(g_Whx[0], g_Whx[1], i, w_hx[i]);
    if (i < 512*512){ spst(g_Wt[0], g_Wt[1], i, w_t[i]); spst(g_Whh[0], g_Whh[1], i, w_hh[i]); }
    if (i < 1024*512){
        int r = i >> 9, c = i & 511;
        spst(g_Wrzh[0], g_Wrzh[1], i, (r < 512) ? w_rh[r*512+c] : w_zh[(r-512)*512+c]);
    }
    if (i < 512*WD_) spst(g_We[0], g_We[1], i, w_e[i]);
}

// ---------- HMMA GEMM core: 128xBN tile, K32 chunks, bf16x3 split ----------
// swizzled 64B rows (no padding): byte addr = r*64 + ((c ^ ((r>>1)&3))*16)
// 3 stages, ONE __syncthreads per chunk, prefetch distance 2.
#define MSZ 8192             // 128 rows * 64 B
#define STG (4*MSZ)          // Ah | Al | Bh | Bl = 32768
#define NSTG 3
#define SMB (NSTG*STG)       // 98304 -> 2 CTAs/SM

__device__ __forceinline__ u32 swz(int r, int c){
    return (u32)(r*64 + ((c ^ ((r>>1)&3))<<4));
}

template<int MODE, int K, int CH, int BN>
__device__ __forceinline__ void gemm_tile(const u32 smu, int bm, int bn, int t,
    const float* __restrict__ bias, const float* __restrict__ bias2, float* __restrict__ out)
{
    const int tid = threadIdx.x, lane = tid & 31, wid = tid >> 5;
    constexpr int MI = (BN == 128) ? 2 : 1;
    const int m0 = (BN == 128) ? (wid >> 1)*32 : wid*16;
    const int n0 = (BN == 128) ? (wid & 1)*64 : 0;

    const bf16 *BH, *BL;
    if      (MODE==0){ BH=g_We[0];   BL=g_We[1];   }
    else if (MODE==1){ BH=g_Wrz[0];  BL=g_Wrz[1];  }
    else if (MODE==2){ BH=g_Wo[0];   BL=g_Wo[1];   }
    else if (MODE==3){ BH=g_Whx[0];  BL=g_Whx[1];  }
    else if (MODE==4){ BH=g_Wt[0];   BL=g_Wt[1];   }
    else if (MODE==5){ BH=g_Wrzh[0]; BL=g_Wrzh[1]; }
    else             { BH=g_Whh[0];  BL=g_Whh[1];  }

    float acc[MI][8][4];
#pragma unroll
    for (int a=0;a<MI;a++)
#pragma unroll
        for (int b=0;b<8;b++)
#pragma unroll
            for (int c=0;c<4;c++) acc[a][b][c] = 0.f;

    auto issue = [&](int ch){
        const int k0 = ch*32;
        const u32 sbase = smu + (u32)((ch % NSTG)*STG);
#pragma unroll
        for (int it = 0; it < 2; it++){
            int g = tid + it*256;
            int r = g >> 2, c = g & 3;
            int kk = k0 + c*8;
            int gm = bm + r;
            u32 so = sbase + swz(r, c);
            const bf16 *pH = g_x[0], *pL = g_x[1];
            int sz = 16;
            if (MODE == 0){
                pH = g_xw[0]+gm*WD_+kk; pL = g_xw[1]+gm*WD_+kk;
            } else if (MODE == 1){
                if (kk < I_){ pH = g_x[0]+gm*I_+kk; pL = g_x[1]+gm*I_+kk; }
                else        { pH = g_e[0]+gm*H_+kk-I_; pL = g_e[1]+gm*H_+kk-I_; }
            } else if (MODE == 2){
                int seg = kk >> 7, sh = (seg==0) ? 1 : (seg==1) ? 7 : 30;
                int b = gm / T_;
                if (b >= sh){ int s0 = (gm - sh*T_)*I_ + (kk & 127); pH = g_x[0]+s0; pL = g_x[1]+s0; }
                else sz = 0;
            } else if (MODE == 3){ pH = g_x[0]+gm*I_+kk;  pL = g_x[1]+gm*I_+kk; }
            else if (MODE == 4){ pH = g_h[0]+gm*H_+kk;    pL = g_h[1]+gm*H_+kk; }
            else if (MODE == 5){ pH = g_hob[0]+gm*H_+kk;  pL = g_hob[1]+gm*H_+kk; }
            else               { pH = g_ab[0]+gm*H_+kk;   pL = g_ab[1]+gm*H_+kk; }
            cpa(so, pH, sz); cpa(so + MSZ, pL, sz);

            if (r < BN){
                int gn = bn + r;
                cpa(so + 2*MSZ, BH + gn*K + kk, 16); cpa(so + 3*MSZ, BL + gn*K + kk, 16);
            }
        }
        cpcommit();
    };

    // per-lane ldmatrix bases (row part + swizzle key)
    const int arow = m0 + (lane&7) + ((lane>>3)&1)*8;
    const u32 aoff = (u32)(arow*64);
    const int axr = (arow>>1)&3, ac0 = (lane>>4)&1;
    const int brow = n0 + (lane&7) + ((lane>>4)&1)*8;
    const u32 boff = (u32)(brow*64);
    const int bxr = (brow>>1)&3, bc0 = (lane>>3)&1;

    __syncthreads();        // protect stage buffers across consecutive tiles
    issue(0);
    if (1 < CH) issue(1);

#pragma unroll 1
    for (int ch = 0; ch < CH; ch++){
        if (ch + 1 < CH) cpwait<1>(); else cpwait<0>();
        __syncthreads();                       // single barrier per chunk
        if (ch + 2 < CH) issue(ch + 2);

        const u32 sbase = smu + (u32)((ch % NSTG)*STG);
#pragma unroll
        for (int ks = 0; ks < 2; ks++){
            const u32 aAd = sbase + aoff + (u32)((((ac0 + 2*ks) ^ axr))<<4);
            const u32 bAd = sbase + 2*MSZ + boff + (u32)((((bc0 + 2*ks) ^ bxr))<<4);
            u32 ah[MI][4], al[MI][4], bh[4][4], bl[4][4];
            ldsm4(ah[0], aAd);
            ldsm4(al[0], aAd + MSZ);
            if (MI == 2){
                ldsm4(ah[1], aAd + 1024);          // +16 rows (swizzle key invariant)
                ldsm4(al[1], aAd + MSZ + 1024);
            }
#pragma unroll
            for (int nq = 0; nq < 4; nq++){
                ldsm4(bh[nq], bAd + nq*1024);
                ldsm4(bl[nq], bAd + MSZ + nq*1024);
            }
#pragma unroll
            for (int ni = 0; ni < 8; ni++){
                const u32* ph = &bh[ni>>1][(ni&1)*2];
                mmab(acc[0][ni], ah[0], ph);
                if (MI == 2) mmab(acc[1][ni], ah[1], ph);
            }
#pragma unroll
            for (int ni = 0; ni < 8; ni++){
                const u32* pl = &bl[ni>>1][(ni&1)*2];
                mmab(acc[0][ni], ah[0], pl);
                if (MI == 2) mmab(acc[1][ni], ah[1], pl);
            }
#pragma unroll
            for (int ni = 0; ni < 8; ni++){
                const u32* ph = &bh[ni>>1][(ni&1)*2];
                mmab(acc[0][ni], al[0], ph);
                if (MI == 2) mmab(acc[1][ni], al[1], ph);
            }
        }
    }

    // ---------- epilogue ----------
#pragma unroll
    for (int mi = 0; mi < MI; mi++){
#pragma unroll
        for (int half = 0; half < 2; half++){
            const int gm = bm + m0 + mi*16 + (lane>>2) + half*8;
#pragma unroll
            for (int ni = 0; ni < 8; ni++){
                const int gn = bn + n0 + ni*8 + (lane&3)*2;
                float v0 = acc[mi][ni][half*2+0];
                float v1 = acc[mi][ni][half*2+1];
                if (MODE == 0){
                    spst(g_e[0], g_e[1], gm*H_+gn,   sigf(v0 + bias[gn]));
                    spst(g_e[0], g_e[1], gm*H_+gn+1, sigf(v1 + bias[gn+1]));
                } else if (MODE == 1){
                    int b = gm/T_, tt = gm - b*T_; int base = (tt*B_ + b)*H_;
                    if (gn < H_){
                        g_pre_r[base+gn]   = v0 + bias[gn];
                        g_pre_r[base+gn+1] = v1 + bias[gn+1];
                    } else {
                        g_pre_z[base+gn-H_]   = v0 + bias2[gn-H_];
                        g_pre_z[base+gn-H_+1] = v1 + bias2[gn-H_+1];
                    }
                } else if (MODE == 2){
                    int b = gm/T_, tt = gm - b*T_; int base = (tt*B_ + b)*H_;
                    g_pre_o[base+gn] = v0; g_pre_o[base+gn+1] = v1;
                } else if (MODE == 3){
                    int b = gm/T_, tt = gm - b*T_; int base = (tt*B_ + b)*H_;
                    g_pre_h[base+gn]   = v0 + bias[gn];
                    g_pre_h[base+gn+1] = v1 + bias[gn+1];
                } else if (MODE == 4){
                    int pb = (t*B_ + gm)*H_ + gn, hb = gm*H_ + gn;
                    float h0 = sigf(g_pre_o[pb]   + v0);
                    float h1 = sigf(g_pre_o[pb+1] + v1);
                    g_ho[hb] = h0; g_ho[hb+1] = h1;
                    spst(g_hob[0], g_hob[1], hb,   h0);
                    spst(g_hob[0], g_hob[1], hb+1, h1);
                } else if (MODE == 5){
                    if (gn < H_){
                        int pb = (t*B_ + gm)*H_ + gn, hb = gm*H_ + gn;
                        float r0 = sigf(g_pre_r[pb]   + v0);
                        float r1 = sigf(g_pre_r[pb+1] + v1);
                        spst(g_ab[0], g_ab[1], hb,   r0 * g_ho[hb]);
                        spst(g_ab[0], g_ab[1], hb+1, r1 * g_ho[hb+1]);
                    } else {
                        int n2 = gn - H_;
                        int pb = (t*B_ + gm)*H_ + n2, hb = gm*H_ + n2;
                        g_z[hb]   = sigf(g_pre_z[pb]   + v0);
                        g_z[hb+1] = sigf(g_pre_z[pb+1] + v1);
                    }
                } else {
                    int pb = (t*B_ + gm)*H_ + gn, hb = gm*H_ + gn;
                    float ht0 = tanhf(g_pre_h[pb]   + v0);
                    float ht1 = tanhf(g_pre_h[pb+1] + v1);
                    float z0 = g_z[hb], z1 = g_z[hb+1];
                    float h0 = (1.f - z0)*g_ho[hb]   + z0*ht0;
                    float h1 = (1.f - z1)*g_ho[hb+1] + z1*ht1;
                    spst(g_h[0], g_h[1], hb,   h0);
                    spst(g_h[0], g_h[1], hb+1, h1);
                    out[(gm*T_ + t)*H_ + gn]   = h0;
                    out[(gm*T_ + t)*H_ + gn+1] = h1;
                }
            }
        }
    }
}

// ---------- precompute kernels ----------
template<int MODE, int K, int CH>
__global__ void __launch_bounds__(256, 2)
mm_k(const float* __restrict__ bias, const float* __restrict__ bias2,
     float* __restrict__ out, int t)
{
    extern __shared__ __align__(128) char sm_[];
    gemm_tile<MODE, K, CH, 128>(s2u(sm_), blockIdx.y*128, blockIdx.x*128, t, bias, bias2, out);
}

// ---------- persistent recurrence: 256 CTAs (2/SM), all phases full-width ----------
__global__ void __launch_bounds__(256, 2)
rec_k(float* __restrict__ out)
{
    extern __shared__ __align__(128) char sm_[];
    const u32 smu = s2u(sm_);
    const int q = blockIdx.x;   // 0..255
    const int bm = (q >> 3)*128;
#pragma unroll 1
    for (int t = 0; t < T_; t++){
        gemm_tile<4,512,16, 64>(smu, bm, (q&7)*64,  t, nullptr, nullptr, nullptr);
        gbar();
        gemm_tile<5,512,16,128>(smu, bm, (q&7)*128, t, nullptr, nullptr, nullptr);
        gbar();
        gemm_tile<6,512,16, 64>(smu, bm, (q&7)*64,  t, nullptr, nullptr, out);
        gbar();
    }
}

// ---------- launcher ----------
extern "C" void kernel_launch(void* const* d_in, const int* in_sizes, int n_in,
                              void* d_out, int out_size)
{
    const float* x    = (const float*)d_in[0];
    const float* xw   = (const float*)d_in[1];
    const float* w_rx = (const float*)d_in[2];
    const float* w_rh = (const float*)d_in[3];
    const float* w_re = (const float*)d_in[4];
    const float* b_r  = (const float*)d_in[5];
    const float* w_zx = (const float*)d_in[6];
    const float* w_zh = (const float*)d_in[7];
    const float* w_ze = (const float*)d_in[8];
    const float* b_z  = (const float*)d_in[9];
    const float* w_hx = (const float*)d_in[10];
    const float* w_hh = (const float*)d_in[11];
    const float* b_h  = (const float*)d_in[12];
    const float* w_d  = (const float*)d_in[13];
    const float* w_w  = (const float*)d_in[14];
    const float* w_m  = (const float*)d_in[15];
    const float* w_t  = (const float*)d_in[16];
    const float* w_e  = (const float*)d_in[17];
    const float* b_e  = (const float*)d_in[18];
    float* out = (float*)d_out;

    cudaFuncSetAttribute(mm_k<0, 32, 1>, cudaFuncAttributeMaxDynamicSharedMemorySize, SMB);
    cudaFuncSetAttribute(mm_k<1,640,20>, cudaFuncAttributeMaxDynamicSharedMemorySize, SMB);
    cudaFuncSetAttribute(mm_k<2,384,12>, cudaFuncAttributeMaxDynamicSharedMemorySize, SMB);
    cudaFuncSetAttribute(mm_k<3,128, 4>, cudaFuncAttributeMaxDynamicSharedMemorySize, SMB);
    cudaFuncSetAttribute(rec_k,          cudaFuncAttributeMaxDynamicSharedMemorySize, SMB);

    prep_k<<<(M_*I_ + 255)/256, 256>>>(x, xw, w_rx, w_rh, w_re, w_zx, w_zh, w_ze,
                                       w_hx, w_hh, w_d, w_w, w_m, w_t, w_e);

    mm_k<0, 32, 1><<<dim3(4,768), 256, SMB>>>(b_e, nullptr, nullptr, 0);
    mm_k<1,640,20><<<dim3(8,768), 256, SMB>>>(b_r, b_z,    nullptr, 0);
    mm_k<2,384,12><<<dim3(4,768), 256, SMB>>>(nullptr, nullptr, nullptr, 0);
    mm_k<3,128, 4><<<dim3(4,768), 256, SMB>>>(b_h, nullptr, nullptr, 0);

    rec_k<<<NCTA, 256, SMB>>>(out);
}

// round 13
// speedup vs baseline: 2.7777x; 1.0439x over previous
#include <cuda_runtime.h>
#include <cuda_bf16.h>
#include <cstdint>

#define B_ 4096
#define T_ 24
#define I_ 128
#define H_ 512
#define WD_ 32
#define M_ (B_*T_)

typedef unsigned int u32; typedef unsigned long long u64; typedef __nv_bfloat16 bf16;

// ---------- scratch (device globals; [0]=hi, [1]=lo) ----------
__device__ __align__(16) bf16 g_x[2][M_*I_], g_xw[2][M_*WD_], g_e[2][M_*H_];
__device__ __align__(16) float g_pre_o[M_*H_], g_pre_r[M_*H_], g_pre_z[M_*H_], g_pre_h[M_*H_];
__device__ __align__(16) bf16 g_h[2][B_*H_], g_hob[2][B_*H_], g_ab[2][B_*H_];
__device__ __align__(16) float g_ho[B_*H_], g_z[B_*H_];
__device__ __align__(16) bf16 g_Wrz[2][1024*640], g_Wo[2][512*384], g_Whx[2][512*128];
__device__ __align__(16) bf16 g_Wt[2][512*512], g_Wrzh[2][1024*512], g_Whh[2][512*512], g_We[2][512*WD_];

__device__ __forceinline__ float sigf(float x){ return 1.f/(1.f + __expf(-x)); }
__device__ __forceinline__ void spst(bf16* hi, bf16* lo, int idx, float v){
    bf16 h = __float2bfloat16(v);
    hi[idx] = h; lo[idx] = __float2bfloat16(v - __bfloat162float(h));
}
__device__ __forceinline__ u32 s2u(const void* p){
    u32 a; asm("{ .reg .u64 t; cvta.to.shared.u64 t, %1; cvt.u32.u64 %0, t; }" : "=r"(a) : "l"(p)); return a;
}
__device__ __forceinline__ void ldsm4(u32* r, u32 addr){
    asm volatile("ldmatrix.sync.aligned.m8n8.x4.shared.b16 {%0,%1,%2,%3}, [%4];"
        : "=r"(r[0]), "=r"(r[1]), "=r"(r[2]), "=r"(r[3]) : "r"(addr));
}
__device__ __forceinline__ void mmab(float* c, const u32* a, const u32* b){
    asm volatile("mma.sync.aligned.m16n8k16.row.col.f32.bf16.bf16.f32 "
        "{%0,%1,%2,%3}, {%4,%5,%6,%7}, {%8,%9}, {%0,%1,%2,%3};"
        : "+f"(c[0]), "+f"(c[1]), "+f"(c[2]), "+f"(c[3])
        : "r"(a[0]), "r"(a[1]), "r"(a[2]), "r"(a[3]), "r"(b[0]), "r"(b[1]));
}
__device__ __forceinline__ void cpa(u32 s, const void* g, int sz){
    asm volatile("cp.async.cg.shared.global [%0], [%1], 16, %2;" :: "r"(s), "l"(g), "r"(sz) : "memory");
}
__device__ __forceinline__ void cpcommit(){ asm volatile("cp.async.commit_group;" ::: "memory"); }
template<int N> __device__ __forceinline__ void cpwait(){ asm volatile("cp.async.wait_group %0;" :: "n"(N) : "memory"); }

// cluster-scope barrier: orders prior global writes (release) and makes peer
// writes visible after wait (acquire + L1 invalidate). 8-CTA scope only.
__device__ __forceinline__ void csync(){
    __threadfence();
    asm volatile("barrier.cluster.arrive.aligned;" ::: "memory");
    asm volatile("barrier.cluster.wait.aligned;" ::: "memory");
}

// ---------- prep ----------
__global__ void prep_k(const float* __restrict__ x, const float* __restrict__ xw,
    const float* __restrict__ w_rx, const float* __restrict__ w_rh, const float* __restrict__ w_re,
    const float* __restrict__ w_zx, const float* __restrict__ w_zh, const float* __restrict__ w_ze,
    const float* __restrict__ w_hx, const float* __restrict__ w_hh,
    const float* __restrict__ w_d,  const float* __restrict__ w_w,  const float* __restrict__ w_m,
    const float* __restrict__ w_t,  const float* __restrict__ w_e)
{
    int i = blockIdx.x*256 + threadIdx.x;
    if (i < M_*I_)  spst(g_x[0],  g_x[1],  i, x[i]);
    if (i < M_*WD_) spst(g_xw[0], g_xw[1], i, xw[i]);
    if (i < B_*H_){ g_h[0][i] = __float2bfloat16(0.f); g_h[1][i] = __float2bfloat16(0.f); }
    if (i < 1024*640){
        int r = i/640, c = i - r*640; float v;
        if (r < 512) v = (c < 128) ? w_rx[r*128+c] : w_re[r*512 + c - 128];
        else { int rr = r-512; v = (c < 128) ? w_zx[rr*128+c] : w_ze[rr*512 + c - 128]; }
        spst(g_Wrz[0], g_Wrz[1], i, v);
    }
    if (i < 512*384){
        int r = i/384, c = i - r*384; int s = c >> 7;
        const float* p = (s==0) ? w_d : (s==1) ? w_w : w_m;
        spst(g_Wo[0], g_Wo[1], i, p[r*128 + (c & 127)]);
    }
    if (i < 512*128) spst(g_Whx[0], g_Whx[1], i, w_hx[i]);
    if (i < 512*512){ spst(g_Wt[0], g_Wt[1], i, w_t[i]); spst(g_Whh[0], g_Whh[1], i, w_hh[i]); }
    if (i < 1024*512){
        int r = i >> 9, c = i & 511;
        spst(g_Wrzh[0], g_Wrzh[1], i, (r < 512) ? w_rh[r*512+c] : w_zh[(r-512)*512+c]);
    }
    if (i < 512*WD_) spst(g_We[0], g_We[1], i, w_e[i]);
}

// ---------- HMMA GEMM core: 128xBN tile, K32 chunks, bf16x3 split ----------
// swizzled 64B rows (no padding): byte addr = r*64 + ((c ^ ((r>>1)&3))*16)
// 3 stages, ONE __syncthreads per chunk, prefetch distance 2.
#define MSZ 8192             // 128 rows * 64 B
#define STG (4*MSZ)          // Ah | Al | Bh | Bl = 32768
#define NSTG 3
#define SMB (NSTG*STG)       // 98304 -> 2 CTAs/SM

__device__ __forceinline__ u32 swz(int r, int c){
    return (u32)(r*64 + ((c ^ ((r>>1)&3))<<4));
}

template<int MODE, int K, int CH, int BN>
__device__ __forceinline__ void gemm_tile(const u32 smu, int bm, int bn, int t,
    const float* __restrict__ bias, const float* __restrict__ bias2, float* __restrict__ out)
{
    const int tid = threadIdx.x, lane = tid & 31, wid = tid >> 5;
    constexpr int MI = (BN == 128) ? 2 : 1;
    const int m0 = (BN == 128) ? (wid >> 1)*32 : wid*16;
    const int n0 = (BN == 128) ? (wid & 1)*64 : 0;

    const bf16 *BH, *BL;
    if      (MODE==0){ BH=g_We[0];   BL=g_We[1];   }
    else if (MODE==1){ BH=g_Wrz[0];  BL=g_Wrz[1];  }
    else if (MODE==2){ BH=g_Wo[0];   BL=g_Wo[1];   }
    else if (MODE==3){ BH=g_Whx[0];  BL=g_Whx[1];  }
    else if (MODE==4){ BH=g_Wt[0];   BL=g_Wt[1];   }
    else if (MODE==5){ BH=g_Wrzh[0]; BL=g_Wrzh[1]; }
    else             { BH=g_Whh[0];  BL=g_Whh[1];  }

    float acc[MI][8][4];
#pragma unroll
    for (int a=0;a<MI;a++)
#pragma unroll
        for (int b=0;b<8;b++)
#pragma unroll
            for (int c=0;c<4;c++) acc[a][b][c] = 0.f;

    auto issue = [&](int ch){
        const int k0 = ch*32;
        const u32 sbase = smu + (u32)((ch % NSTG)*STG);
#pragma unroll
        for (int it = 0; it < 2; it++){
            int g = tid + it*256;
            int r = g >> 2, c = g & 3;
            int kk = k0 + c*8;
            int gm = bm + r;
            u32 so = sbase + swz(r, c);
            const bf16 *pH = g_x[0], *pL = g_x[1];
            int sz = 16;
            if (MODE == 0){
                pH = g_xw[0]+gm*WD_+kk; pL = g_xw[1]+gm*WD_+kk;
            } else if (MODE == 1){
                if (kk < I_){ pH = g_x[0]+gm*I_+kk; pL = g_x[1]+gm*I_+kk; }
                else        { pH = g_e[0]+gm*H_+kk-I_; pL = g_e[1]+gm*H_+kk-I_; }
            } else if (MODE == 2){
                int seg = kk >> 7, sh = (seg==0) ? 1 : (seg==1) ? 7 : 30;
                int b = gm / T_;
                if (b >= sh){ int s0 = (gm - sh*T_)*I_ + (kk & 127); pH = g_x[0]+s0; pL = g_x[1]+s0; }
                else sz = 0;
            } else if (MODE == 3){ pH = g_x[0]+gm*I_+kk;  pL = g_x[1]+gm*I_+kk; }
            else if (MODE == 4){ pH = g_h[0]+gm*H_+kk;    pL = g_h[1]+gm*H_+kk; }
            else if (MODE == 5){ pH = g_hob[0]+gm*H_+kk;  pL = g_hob[1]+gm*H_+kk; }
            else               { pH = g_ab[0]+gm*H_+kk;   pL = g_ab[1]+gm*H_+kk; }
            cpa(so, pH, sz); cpa(so + MSZ, pL, sz);

            if (r < BN){
                int gn = bn + r;
                cpa(so + 2*MSZ, BH + gn*K + kk, 16); cpa(so + 3*MSZ, BL + gn*K + kk, 16);
            }
        }
        cpcommit();
    };

    // per-lane ldmatrix bases (row part + swizzle key)
    const int arow = m0 + (lane&7) + ((lane>>3)&1)*8;
    const u32 aoff = (u32)(arow*64);
    const int axr = (arow>>1)&3, ac0 = (lane>>4)&1;
    const int brow = n0 + (lane&7) + ((lane>>4)&1)*8;
    const u32 boff = (u32)(brow*64);
    const int bxr = (brow>>1)&3, bc0 = (lane>>3)&1;

    __syncthreads();        // protect stage buffers across consecutive tiles
    issue(0);
    if (1 < CH) issue(1);

#pragma unroll 1
    for (int ch = 0; ch < CH; ch++){
        if (ch + 1 < CH) cpwait<1>(); else cpwait<0>();
        __syncthreads();                       // single barrier per chunk
        if (ch + 2 < CH) issue(ch + 2);

        const u32 sbase = smu + (u32)((ch % NSTG)*STG);
#pragma unroll
        for (int ks = 0; ks < 2; ks++){
            const u32 aAd = sbase + aoff + (u32)((((ac0 + 2*ks) ^ axr))<<4);
            const u32 bAd = sbase + 2*MSZ + boff + (u32)((((bc0 + 2*ks) ^ bxr))<<4);
            u32 ah[MI][4], al[MI][4], bh[4][4], bl[4][4];
            ldsm4(ah[0], aAd);
            ldsm4(al[0], aAd + MSZ);
            if (MI == 2){
                ldsm4(ah[1], aAd + 1024);          // +16 rows (swizzle key invariant)
                ldsm4(al[1], aAd + MSZ + 1024);
            }
#pragma unroll
            for (int nq = 0; nq < 4; nq++){
                ldsm4(bh[nq], bAd + nq*1024);
                ldsm4(bl[nq], bAd + MSZ + nq*1024);
            }
#pragma unroll
            for (int ni = 0; ni < 8; ni++){
                const u32* ph = &bh[ni>>1][(ni&1)*2];
                mmab(acc[0][ni], ah[0], ph);
                if (MI == 2) mmab(acc[1][ni], ah[1], ph);
            }
#pragma unroll
            for (int ni = 0; ni < 8; ni++){
                const u32* pl = &bl[ni>>1][(ni&1)*2];
                mmab(acc[0][ni], ah[0], pl);
                if (MI == 2) mmab(acc[1][ni], ah[1], pl);
            }
#pragma unroll
            for (int ni = 0; ni < 8; ni++){
                const u32* ph = &bh[ni>>1][(ni&1)*2];
                mmab(acc[0][ni], al[0], ph);
                if (MI == 2) mmab(acc[1][ni], al[1], ph);
            }
        }
    }

    // ---------- epilogue ----------
#pragma unroll
    for (int mi = 0; mi < MI; mi++){
#pragma unroll
        for (int half = 0; half < 2; half++){
            const int gm = bm + m0 + mi*16 + (lane>>2) + half*8;
#pragma unroll
            for (int ni = 0; ni < 8; ni++){
                const int gn = bn + n0 + ni*8 + (lane&3)*2;
                float v0 = acc[mi][ni][half*2+0];
                float v1 = acc[mi][ni][half*2+1];
                if (MODE == 0){
                    spst(g_e[0], g_e[1], gm*H_+gn,   sigf(v0 + bias[gn]));
                    spst(g_e[0], g_e[1], gm*H_+gn+1, sigf(v1 + bias[gn+1]));
                } else if (MODE == 1){
                    int b = gm/T_, tt = gm - b*T_; int base = (tt*B_ + b)*H_;
                    if (gn < H_){
                        g_pre_r[base+gn]   = v0 + bias[gn];
                        g_pre_r[base+gn+1] = v1 + bias[gn+1];
                    } else {
                        g_pre_z[base+gn-H_]   = v0 + bias2[gn-H_];
                        g_pre_z[base+gn-H_+1] = v1 + bias2[gn-H_+1];
                    }
                } else if (MODE == 2){
                    int b = gm/T_, tt = gm - b*T_; int base = (tt*B_ + b)*H_;
                    g_pre_o[base+gn] = v0; g_pre_o[base+gn+1] = v1;
                } else if (MODE == 3){
                    int b = gm/T_, tt = gm - b*T_; int base = (tt*B_ + b)*H_;
                    g_pre_h[base+gn]   = v0 + bias[gn];
                    g_pre_h[base+gn+1] = v1 + bias[gn+1];
                } else if (MODE == 4){
                    int pb = (t*B_ + gm)*H_ + gn, hb = gm*H_ + gn;
                    float h0 = sigf(g_pre_o[pb]   + v0);
                    float h1 = sigf(g_pre_o[pb+1] + v1);
                    g_ho[hb] = h0; g_ho[hb+1] = h1;
                    spst(g_hob[0], g_hob[1], hb,   h0);
                    spst(g_hob[0], g_hob[1], hb+1, h1);
                } else if (MODE == 5){
                    if (gn < H_){
                        int pb = (t*B_ + gm)*H_ + gn, hb = gm*H_ + gn;
                        float r0 = sigf(g_pre_r[pb]   + v0);
                        float r1 = sigf(g_pre_r[pb+1] + v1);
                        spst(g_ab[0], g_ab[1], hb,   r0 * g_ho[hb]);
                        spst(g_ab[0], g_ab[1], hb+1, r1 * g_ho[hb+1]);
                    } else {
                        int n2 = gn - H_;
                        int pb = (t*B_ + gm)*H_ + n2, hb = gm*H_ + n2;
                        g_z[hb]   = sigf(g_pre_z[pb]   + v0);
                        g_z[hb+1] = sigf(g_pre_z[pb+1] + v1);
                    }
                } else {
                    int pb = (t*B_ + gm)*H_ + gn, hb = gm*H_ + gn;
                    float ht0 = tanhf(g_pre_h[pb]   + v0);
                    float ht1 = tanhf(g_pre_h[pb+1] + v1);
                    float z0 = g_z[hb], z1 = g_z[hb+1];
                    float h0 = (1.f - z0)*g_ho[hb]   + z0*ht0;
                    float h1 = (1.f - z1)*g_ho[hb+1] + z1*ht1;
                    spst(g_h[0], g_h[1], hb,   h0);
                    spst(g_h[0], g_h[1], hb+1, h1);
                    out[(gm*T_ + t)*H_ + gn]   = h0;
                    out[(gm*T_ + t)*H_ + gn+1] = h1;
                }
            }
        }
    }
}

// ---------- precompute kernels ----------
template<int MODE, int K, int CH>
__global__ void __launch_bounds__(256, 2)
mm_k(const float* __restrict__ bias, const float* __restrict__ bias2,
     float* __restrict__ out, int t)
{
    extern __shared__ __align__(128) char sm_[];
    gemm_tile<MODE, K, CH, 128>(s2u(sm_), blockIdx.y*128, blockIdx.x*128, t, bias, bias2, out);
}

// ---------- recurrence: 32 independent clusters of 8 CTAs, one 128-row block each ----------
// All cross-CTA dataflow (ho/z/a/h) is within the cluster's row block; clusters
// never communicate, so wave execution is safe and no grid-wide sync exists.
__global__ void __launch_bounds__(256, 2) __cluster_dims__(8, 1, 1)
rec_k(float* __restrict__ out)
{
    extern __shared__ __align__(128) char sm_[];
    const u32 smu = s2u(sm_);
    const int q = blockIdx.x;          // 0..255; cluster = q>>3, rank = q&7
    const int bm = (q >> 3)*128;
#pragma unroll 1
    for (int t = 0; t < T_; t++){
        gemm_tile<4,512,16, 64>(smu, bm, (q&7)*64,  t, nullptr, nullptr, nullptr);
        csync();
        gemm_tile<5,512,16,128>(smu, bm, (q&7)*128, t, nullptr, nullptr, nullptr);
        csync();
        gemm_tile<6,512,16, 64>(smu, bm, (q&7)*64,  t, nullptr, nullptr, out);
        csync();
    }
}

// ---------- launcher ----------
extern "C" void kernel_launch(void* const* d_in, const int* in_sizes, int n_in,
                              void* d_out, int out_size)
{
    const float* x    = (const float*)d_in[0];
    const float* xw   = (const float*)d_in[1];
    const float* w_rx = (const float*)d_in[2];
    const float* w_rh = (const float*)d_in[3];
    const float* w_re = (const float*)d_in[4];
    const float* b_r  = (const float*)d_in[5];
    const float* w_zx = (const float*)d_in[6];
    const float* w_zh = (const float*)d_in[7];
    const float* w_ze = (const float*)d_in[8];
    const float* b_z  = (const float*)d_in[9];
    const float* w_hx = (const float*)d_in[10];
    const float* w_hh = (const float*)d_in[11];
    const float* b_h  = (const float*)d_in[12];
    const float* w_d  = (const float*)d_in[13];
    const float* w_w  = (const float*)d_in[14];
    const float* w_m  = (const float*)d_in[15];
    const float* w_t  = (const float*)d_in[16];
    const float* w_e  = (const float*)d_in[17];
    const float* b_e  = (const float*)d_in[18];
    float* out = (float*)d_out;

    cudaFuncSetAttribute(mm_k<0, 32, 1>, cudaFuncAttributeMaxDynamicSharedMemorySize, SMB);
    cudaFuncSetAttribute(mm_k<1,640,20>, cudaFuncAttributeMaxDynamicSharedMemorySize, SMB);
    cudaFuncSetAttribute(mm_k<2,384,12>, cudaFuncAttributeMaxDynamicSharedMemorySize, SMB);
    cudaFuncSetAttribute(mm_k<3,128, 4>, cudaFuncAttributeMaxDynamicSharedMemorySize, SMB);
    cudaFuncSetAttribute(rec_k,          cudaFuncAttributeMaxDynamicSharedMemorySize, SMB);

    prep_k<<<(M_*I_ + 255)/256, 256>>>(x, xw, w_rx, w_rh, w_re, w_zx, w_zh, w_ze,
                                       w_hx, w_hh, w_d, w_w, w_m, w_t, w_e);

    mm_k<0, 32, 1><<<dim3(4,768), 256, SMB>>>(b_e, nullptr, nullptr, 0);
    mm_k<1,640,20><<<dim3(8,768), 256, SMB>>>(b_r, b_z,    nullptr, 0);
    mm_k<2,384,12><<<dim3(4,768), 256, SMB>>>(nullptr, nullptr, nullptr, 0);
    mm_k<3,128, 4><<<dim3(4,768), 256, SMB>>>(b_h, nullptr, nullptr, 0);

    rec_k<<<256, 256, SMB>>>(out);
}